// round 3
// baseline (speedup 1.0000x reference)
#include <cuda_runtime.h>
#include <math.h>

// ---------------- problem constants ----------------
#define D_MODEL 768
#define N_HEADS 12
#define D_HEAD  64
#define N_MEM   3072
#define BB      8
#define SS      1024
#define ROWS    (BB*SS)        // 8192
#define ZB      (BB*N_HEADS)   // 96 batched (b,h) slices
#define ALPHA_F 0.1f
#define EPS_F   1e-5f
#define NSTEPS  12

// ---------------- scratch layout (floats) ----------------
constexpr long L_G   = (long)ROWS * D_MODEL;     // 6,291,456
constexpr long L_QK  = (long)ROWS * 1536;        // 12,582,912
constexpr long L_H   = (long)ROWS * N_MEM;       // 25,165,824
constexpr long L_W   = 1536L * 768;              // 1,179,648
constexpr long L_A   = (long)ZB * SS * SS;       // 100,663,296

constexpr long OFF_G     = 0;
constexpr long OFF_QK    = OFF_G     + L_G;
constexpr long OFF_AQAK  = OFF_QK    + L_QK;
constexpr long OFF_GATTN = OFF_AQAK  + L_QK;
constexpr long OFF_GHOP  = OFF_GATTN + L_G;
constexpr long OFF_H     = OFF_GHOP  + L_G;
constexpr long OFF_WQK   = OFF_H     + L_H;
constexpr long OFF_RSTD  = OFF_WQK   + L_W;
constexpr long OFF_MEAN  = OFF_RSTD  + ROWS;
constexpr long OFF_LSE   = OFF_MEAN  + ROWS;
constexpr long OFF_A     = OFF_LSE   + (long)ZB * SS;
constexpr long TOTAL_F   = OFF_A     + L_A;      // ~171.2M floats (~685 MB)

__device__ float g_buf[TOTAL_F];

// ---------------- reductions ----------------
__device__ __forceinline__ float warpReduceSum(float v) {
    #pragma unroll
    for (int o = 16; o > 0; o >>= 1) v += __shfl_xor_sync(0xffffffffu, v, o);
    return v;
}
__device__ __forceinline__ float warpReduceMax(float v) {
    #pragma unroll
    for (int o = 16; o > 0; o >>= 1) v = fmaxf(v, __shfl_xor_sync(0xffffffffu, v, o));
    return v;
}
__device__ __forceinline__ float blockReduceSum(float v) {
    __shared__ float sh[32];
    int lane = threadIdx.x & 31, wid = threadIdx.x >> 5;
    __syncthreads();                 // guard WAR on sh reuse across calls
    v = warpReduceSum(v);
    if (lane == 0) sh[wid] = v;
    __syncthreads();
    int nw = (blockDim.x + 31) >> 5;
    v = (threadIdx.x < nw) ? sh[threadIdx.x] : 0.f;
    if (wid == 0) v = warpReduceSum(v);
    return v;                        // valid in warp 0
}
__device__ __forceinline__ float blockReduceMax(float v) {
    __shared__ float sh[32];
    int lane = threadIdx.x & 31, wid = threadIdx.x >> 5;
    __syncthreads();
    v = warpReduceMax(v);
    if (lane == 0) sh[wid] = v;
    __syncthreads();
    int nw = (blockDim.x + 31) >> 5;
    v = (threadIdx.x < nw) ? sh[threadIdx.x] : -3.4e38f;
    if (wid == 0) v = warpReduceMax(v);
    return v;
}

// ---------------- LN forward ----------------
// g = gamma*(x-mean)*rstd + delta ; store mean, rstd per row.
__global__ void ln_forward_kernel(const float* __restrict__ x,
                                  const float* __restrict__ gamma,
                                  const float* __restrict__ delta,
                                  float* __restrict__ g,
                                  float* __restrict__ rstd_o,
                                  float* __restrict__ mean_o) {
    int row = blockIdx.x;
    const float* xr = x + (long)row * D_MODEL;
    int t = threadIdx.x;                      // 256 threads, 3 elems each
    float v[3]; float s = 0.f;
    #pragma unroll
    for (int i = 0; i < 3; i++) { v[i] = xr[t + i*256]; s += v[i]; }
    s = blockReduceSum(s);
    __shared__ float sh_mean, sh_rstd;
    if (threadIdx.x == 0) sh_mean = s * (1.0f / D_MODEL);
    __syncthreads();
    float mean = sh_mean;
    float q = 0.f;
    #pragma unroll
    for (int i = 0; i < 3; i++) { float d = v[i] - mean; q += d*d; }
    q = blockReduceSum(q);
    if (threadIdx.x == 0) sh_rstd = rsqrtf(q * (1.0f / D_MODEL) + EPS_F);
    __syncthreads();
    float rstd = sh_rstd;
    float gm = gamma[0];
    float* gr = g + (long)row * D_MODEL;
    #pragma unroll
    for (int i = 0; i < 3; i++)
        gr[t + i*256] = gm * (v[i] - mean) * rstd + delta[t + i*256];
    if (threadIdx.x == 0) { rstd_o[row] = rstd; mean_o[row] = mean; }
}

// ---------------- row LSE over scores ----------------
__global__ void lse_kernel(const float* __restrict__ A, float* __restrict__ lse) {
    long row = blockIdx.x;                    // ZB*SS rows of length SS
    const float* ar = A + row * SS;
    int t = threadIdx.x;                      // 256 threads, 4 each
    float v[4]; float m = -3.4e38f;
    #pragma unroll
    for (int i = 0; i < 4; i++) { v[i] = ar[t + i*256]; m = fmaxf(m, v[i]); }
    m = blockReduceMax(m);
    __shared__ float sh_m;
    if (threadIdx.x == 0) sh_m = m;
    __syncthreads();
    m = sh_m;
    float s = 0.f;
    #pragma unroll
    for (int i = 0; i < 4; i++) s += __expf(v[i] - m);
    s = blockReduceSum(s);
    if (threadIdx.x == 0) lse[row] = m + __logf(s);
}

// ---------------- fused LN-backward + update ----------------
// u = x - gattn_pos - ghop_pos ; grad = gamma*rstd*(u - mean(u) - ghat*mean(u*ghat))
__global__ void update_kernel(float* __restrict__ x,
                              const float* __restrict__ ga,
                              const float* __restrict__ gh,
                              const float* __restrict__ gamma,
                              const float* __restrict__ mean_a,
                              const float* __restrict__ rstd_a) {
    int row = blockIdx.x;
    long base = (long)row * D_MODEL;
    int t = threadIdx.x;
    float mean = mean_a[row], rstd = rstd_a[row];
    float xv[3], uv[3], gv[3];
    float s1 = 0.f, s2 = 0.f;
    #pragma unroll
    for (int i = 0; i < 3; i++) {
        long idx = base + t + i*256;
        xv[i] = x[idx];
        uv[i] = xv[i] - ga[idx] - gh[idx];
        gv[i] = (xv[i] - mean) * rstd;
        s1 += uv[i]; s2 += uv[i] * gv[i];
    }
    s1 = blockReduceSum(s1);
    __shared__ float sh1, sh2;
    if (threadIdx.x == 0) sh1 = s1;
    s2 = blockReduceSum(s2);
    if (threadIdx.x == 0) sh2 = s2;
    __syncthreads();
    float mu = sh1 * (1.0f / D_MODEL);
    float mg = sh2 * (1.0f / D_MODEL);
    float gm = gamma[0];
    #pragma unroll
    for (int i = 0; i < 3; i++) {
        float grad = gm * rstd * (uv[i] - mu - gv[i] * mg);
        x[base + t + i*256] = xv[i] - ALPHA_F * grad;
    }
}

// ---------------- generic tiled fp32 GEMM ----------------
// C[m,n] = alpha * sum_k opA(A)[m,k] * opB(B)[k,n]
// TA=0: A[m*lda+k]      TA=1: A[k*lda+m]   (transposed-A storage)
// TB=1: B[n*ldb+k] (NT)  TB=0: B[k*ldb+n]  (NN)
// PRO: 0 none | 1 relu(a) | 2 a=exp(a-lse[m]) | 3 a=exp(a-lse[k])
// Batched over blockIdx.z: z = b*N_HEADS + h; per-operand (b,h) strides.
template<int BM, int BN, int BK, int TM, int TN, int TA, int TB, int PRO>
__global__ void __launch_bounds__((BM/TM)*(BN/TN))
gemm_kernel(const float* __restrict__ A, int lda, long sAb, long sAh,
            const float* __restrict__ B, int ldb, long sBb, long sBh,
            float* __restrict__ C, int ldc, long sCb, long sCh,
            int M, int N, int K,
            const float* __restrict__ lse,
            const float* __restrict__ alphaPtr) {
    constexpr int NT = (BM/TM) * (BN/TN);
    int z  = blockIdx.z;
    int zb = z / N_HEADS, zh = z % N_HEADS;
    A += zb * sAb + zh * sAh;
    B += zb * sBb + zh * sBh;
    C += zb * sCb + zh * sCh;
    const float* lsez = lse ? (lse + (long)z * SS) : nullptr;

    __shared__ float As[BK][BM];
    __shared__ float Bs[BK][BN];
    int bm  = blockIdx.y * BM;
    int bn  = blockIdx.x * BN;
    int tid = threadIdx.x;
    int tx  = tid % (BN / TN);
    int ty  = tid / (BN / TN);

    float acc[TM][TN];
    #pragma unroll
    for (int i = 0; i < TM; i++)
        #pragma unroll
        for (int j = 0; j < TN; j++) acc[i][j] = 0.f;

    for (int k0 = 0; k0 < K; k0 += BK) {
        // --- A tile ---
        #pragma unroll
        for (int r = 0; r < (BM*BK)/NT; r++) {
            int i = tid + r * NT;
            int m, kk; float v;
            if (TA == 0) { m = i / BK; kk = i % BK; v = A[(long)(bm + m) * lda + (k0 + kk)]; }
            else         { kk = i / BM; m = i % BM; v = A[(long)(k0 + kk) * lda + (bm + m)]; }
            if      (PRO == 1) v = fmaxf(v, 0.f);
            else if (PRO == 2) v = __expf(v - lsez[bm + m]);
            else if (PRO == 3) v = __expf(v - lsez[k0 + kk]);
            As[kk][m] = v;
        }
        // --- B tile ---
        #pragma unroll
        for (int r = 0; r < (BN*BK)/NT; r++) {
            int i = tid + r * NT;
            int n, kk; float v;
            if (TB == 1) { n = i / BK; kk = i % BK; v = B[(long)(bn + n) * ldb + (k0 + kk)]; }
            else         { kk = i / BN; n = i % BN; v = B[(long)(k0 + kk) * ldb + (bn + n)]; }
            Bs[kk][n] = v;
        }
        __syncthreads();
        #pragma unroll
        for (int kk = 0; kk < BK; kk++) {
            float af[TM], bf[TN];
            #pragma unroll
            for (int i = 0; i < TM; i++) af[i] = As[kk][ty * TM + i];
            #pragma unroll
            for (int j = 0; j < TN; j++) bf[j] = Bs[kk][tx * TN + j];
            #pragma unroll
            for (int i = 0; i < TM; i++)
                #pragma unroll
                for (int j = 0; j < TN; j++) acc[i][j] += af[i] * bf[j];
        }
        __syncthreads();
    }
    float alpha = alphaPtr ? alphaPtr[zh] : 1.0f;
    #pragma unroll
    for (int i = 0; i < TM; i++)
        #pragma unroll
        for (int j = 0; j < TN; j++)
            C[(long)(bm + ty * TM + i) * ldc + (bn + tx * TN + j)] = alpha * acc[i][j];
}

// ---------------- driver ----------------
extern "C" void kernel_launch(void* const* d_in, const int* in_sizes, int n_in,
                              void* d_out, int out_size) {
    const float* x_in  = (const float*)d_in[0];
    const float* gamma = (const float*)d_in[1];
    const float* delta = (const float*)d_in[2];
    const float* Wq    = (const float*)d_in[3];
    const float* Wk    = (const float*)d_in[4];
    const float* beta  = (const float*)d_in[5];
    const float* xi    = (const float*)d_in[6];
    float* x = (float*)d_out;

    float* buf = nullptr;
    cudaGetSymbolAddress((void**)&buf, g_buf);
    float* G     = buf + OFF_G;
    float* QK    = buf + OFF_QK;
    float* AqAk  = buf + OFF_AQAK;
    float* Gattn = buf + OFF_GATTN;
    float* Ghop  = buf + OFF_GHOP;
    float* Hbuf  = buf + OFF_H;
    float* Wqk   = buf + OFF_WQK;
    float* rstd  = buf + OFF_RSTD;
    float* meanb = buf + OFF_MEAN;
    float* lseb  = buf + OFF_LSE;
    float* Abuf  = buf + OFF_A;

    // x <- input ; Wqk = [Wq ; Wk] concatenated once (weights are constant)
    cudaMemcpyAsync(x, x_in, sizeof(float) * L_G, cudaMemcpyDeviceToDevice);
    cudaMemcpyAsync(Wqk, Wq, sizeof(float) * 768 * 768, cudaMemcpyDeviceToDevice);
    cudaMemcpyAsync(Wqk + 768 * 768, Wk, sizeof(float) * 768 * 768, cudaMemcpyDeviceToDevice);

    const long sA_hd = 1024L * 1536;   // per-batch row-block stride in QK/AqAk
    const long sA_zz = (long)SS * SS;  // per-(b,h) score slice

    for (int step = 0; step < NSTEPS; step++) {
        // 1. LN forward
        ln_forward_kernel<<<ROWS, 256>>>(x, gamma, delta, G, rstd, meanb);

        // 2. QK = g @ Wqk^T  (8192 x 1536, K=768); layout (b,s, h*64+y | 768+h*64+y)
        gemm_kernel<128,128,16,8,8,0,1,0><<<dim3(1536/128, ROWS/128, 1), 256>>>(
            G, D_MODEL, 0, 0, Wqk, D_MODEL, 0, 0,
            QK, 1536, 0, 0, ROWS, 1536, D_MODEL, nullptr, nullptr);

        // 3. scores A = beta_h * Q_bh K_bh^T  (batched 96 x [1024x1024], K=64)
        gemm_kernel<128,128,16,8,8,0,1,0><<<dim3(SS/128, SS/128, ZB), 256>>>(
            QK,        1536, sA_hd, 64,
            QK + 768,  1536, sA_hd, 64,
            Abuf, SS, (long)N_HEADS * sA_zz, sA_zz,
            SS, SS, D_HEAD, nullptr, beta);

        // 4. row lse
        lse_kernel<<<ZB * SS, 256>>>(Abuf, lseb);

        // 5. Aq = P K  -> AqAk[:, h*64+y]   (exp(A - lse[row]) prologue)
        gemm_kernel<128,64,16,8,4,0,0,2><<<dim3(1, SS/128, ZB), 256>>>(
            Abuf, SS, (long)N_HEADS * sA_zz, sA_zz,
            QK + 768, 1536, sA_hd, 64,
            AqAk, 1536, sA_hd, 64,
            SS, D_HEAD, SS, lseb, nullptr);

        // 6. Ak = P^T Q -> AqAk[:, 768+h*64+y] (transposed-A, exp(A - lse[q]))
        gemm_kernel<128,64,16,8,4,1,0,3><<<dim3(1, SS/128, ZB), 256>>>(
            Abuf, SS, (long)N_HEADS * sA_zz, sA_zz,
            QK, 1536, sA_hd, 64,
            AqAk + 768, 1536, sA_hd, 64,
            SS, D_HEAD, SS, lseb, nullptr);

        // 7. Gattn_pos = AqAk @ Wqk  (8192 x 768, K=1536)
        gemm_kernel<128,128,16,8,8,0,0,0><<<dim3(D_MODEL/128, ROWS/128, 1), 256>>>(
            AqAk, 1536, 0, 0, Wqk, D_MODEL, 0, 0,
            Gattn, D_MODEL, 0, 0, ROWS, D_MODEL, 1536, nullptr, nullptr);

        // 8. H = g @ xi^T  (8192 x 3072, K=768)
        gemm_kernel<128,128,16,8,8,0,1,0><<<dim3(N_MEM/128, ROWS/128, 1), 256>>>(
            G, D_MODEL, 0, 0, xi, D_MODEL, 0, 0,
            Hbuf, N_MEM, 0, 0, ROWS, N_MEM, D_MODEL, nullptr, nullptr);

        // 9. Ghop_pos = relu(H) @ xi  (8192 x 768, K=3072)
        gemm_kernel<128,128,16,8,8,0,0,1><<<dim3(D_MODEL/128, ROWS/128, 1), 256>>>(
            Hbuf, N_MEM, 0, 0, xi, D_MODEL, 0, 0,
            Ghop, D_MODEL, 0, 0, ROWS, D_MODEL, N_MEM, nullptr, nullptr);

        // 10. u = x - Gattn - Ghop ; x -= ALPHA * J_LN^T u
        update_kernel<<<ROWS, 256>>>(x, Gattn, Ghop, gamma, meanb, rstd);
    }
}

// round 6
// speedup vs baseline: 2.3818x; 2.3818x over previous
#include <cuda_runtime.h>
#include <cuda_bf16.h>
#include <math.h>
#include <stdint.h>

// ---------------- problem constants ----------------
#define D_MODEL 768
#define N_HEADS 12
#define D_HEAD  64
#define N_MEM   3072
#define BB      8
#define SS      1024
#define ROWS    (BB*SS)        // 8192
#define ZB      (BB*N_HEADS)   // 96
#define ALPHA_F 0.1f
#define EPS_F   1e-5f
#define NSTEPS  12

// ---------------- element counts ----------------
constexpr long NG  = (long)ROWS * D_MODEL;
constexpr long NQK = (long)ROWS * 1536;
constexpr long NP  = (long)ZB * SS * SS;
constexpr long NH  = (long)ROWS * N_MEM;
constexpr long NW  = 1536L * 768;
constexpr long NXI = 3072L * 768;

// bf16 plane pool offsets
constexpr long O_GH  = 0;            constexpr long O_GL  = O_GH  + NG;
constexpr long O_QKH = O_GL  + NG;   constexpr long O_QKL = O_QKH + NQK;
constexpr long O_PH  = O_QKL + NQK;  constexpr long O_PL  = O_PH  + NP;
constexpr long O_AQH = O_PL  + NP;   constexpr long O_AQL = O_AQH + NQK;
constexpr long O_HH  = O_AQL + NQK;  constexpr long O_HL  = O_HH  + NH;
constexpr long O_WH  = O_HL  + NH;   constexpr long O_WL  = O_WH  + NW;
constexpr long O_WTH = O_WL  + NW;   constexpr long O_WTL = O_WTH + NW;
constexpr long O_XH  = O_WTL + NW;   constexpr long O_XL  = O_XH  + NXI;
constexpr long O_XTH = O_XL  + NXI;  constexpr long O_XTL = O_XTH + NXI;
constexpr long TOT_B = O_XTL + NXI;

// fp32 pool offsets
constexpr long F_A    = 0;
constexpr long F_GA   = F_A  + NP;
constexpr long F_GO   = F_GA + NG;
constexpr long F_MEAN = F_GO + NG;
constexpr long F_RSTD = F_MEAN + ROWS;
constexpr long TOT_F  = F_RSTD + ROWS;

__device__ __align__(256) __nv_bfloat16 g_bh[TOT_B];
__device__ __align__(256) float g_fp[TOT_F];

// ---------------- PTX helpers ----------------
__device__ __forceinline__ uint32_t smem_u32(const void* p) {
    uint32_t a;
    asm("{ .reg .u64 t; cvta.to.shared.u64 t, %1; cvt.u32.u64 %0, t; }" : "=r"(a) : "l"(p));
    return a;
}
__device__ __forceinline__ void cp16(uint32_t dst, const void* src) {
    asm volatile("cp.async.cg.shared.global [%0], [%1], 16;" :: "r"(dst), "l"(src));
}
__device__ __forceinline__ void cp_commit() {
    asm volatile("cp.async.commit_group;" ::: "memory");
}
template<int N> __device__ __forceinline__ void cp_wait() {
    asm volatile("cp.async.wait_group %0;" :: "n"(N) : "memory");
}
#define MMA16816(c, a, b) \
    asm volatile("mma.sync.aligned.m16n8k16.row.col.f32.bf16.bf16.f32 " \
        "{%0,%1,%2,%3}, {%4,%5,%6,%7}, {%8,%9}, {%0,%1,%2,%3};" \
        : "+f"(c[0]), "+f"(c[1]), "+f"(c[2]), "+f"(c[3]) \
        : "r"(a[0]), "r"(a[1]), "r"(a[2]), "r"(a[3]), "r"(b[0]), "r"(b[1]))

__device__ __forceinline__ void split_val(float v, __nv_bfloat16& h, __nv_bfloat16& l) {
    h = __float2bfloat16_rn(v);
    l = __float2bfloat16_rn(v - __bfloat162float(h));
}
__device__ __forceinline__ uint32_t lds32(const __nv_bfloat16* p) {
    return *reinterpret_cast<const uint32_t*>(p);
}

// ---------------- reductions ----------------
__device__ __forceinline__ float warpSum(float v) {
    #pragma unroll
    for (int o = 16; o > 0; o >>= 1) v += __shfl_xor_sync(0xffffffffu, v, o);
    return v;
}
__device__ __forceinline__ float warpMax(float v) {
    #pragma unroll
    for (int o = 16; o > 0; o >>= 1) v = fmaxf(v, __shfl_xor_sync(0xffffffffu, v, o));
    return v;
}
__device__ __forceinline__ float blkSum(float v) {
    __shared__ float sh[32];
    int lane = threadIdx.x & 31, wid = threadIdx.x >> 5;
    __syncthreads();
    v = warpSum(v);
    if (lane == 0) sh[wid] = v;
    __syncthreads();
    int nw = (blockDim.x + 31) >> 5;
    v = (threadIdx.x < nw) ? sh[threadIdx.x] : 0.f;
    if (wid == 0) v = warpSum(v);
    return v;
}
__device__ __forceinline__ float blkMax(float v) {
    __shared__ float sh[32];
    int lane = threadIdx.x & 31, wid = threadIdx.x >> 5;
    __syncthreads();
    v = warpMax(v);
    if (lane == 0) sh[wid] = v;
    __syncthreads();
    int nw = (blockDim.x + 31) >> 5;
    v = (threadIdx.x < nw) ? sh[threadIdx.x] : -3.4e38f;
    if (wid == 0) v = warpMax(v);
    return v;
}

// ---------------- prep kernels ----------------
__global__ void split_mat(const float* __restrict__ src,
                          __nv_bfloat16* __restrict__ h, __nv_bfloat16* __restrict__ l) {
    long i = (long)blockIdx.x * 256 + threadIdx.x;
    __nv_bfloat16 a, b; split_val(src[i], a, b);
    h[i] = a; l[i] = b;
}
// dst[c, r] = src[r, c]
__global__ void transpose_split(const float* __restrict__ src, int R, int C,
                                __nv_bfloat16* __restrict__ dh, __nv_bfloat16* __restrict__ dl,
                                int ldD, int colOfs) {
    __shared__ float t[32][33];
    int c0 = blockIdx.x * 32, r0 = blockIdx.y * 32;
    int tx = threadIdx.x, ty = threadIdx.y;
    #pragma unroll
    for (int i = ty; i < 32; i += 8)
        t[i][tx] = src[(long)(r0 + i) * C + c0 + tx];
    __syncthreads();
    #pragma unroll
    for (int i = ty; i < 32; i += 8) {
        __nv_bfloat16 a, b; split_val(t[tx][i], a, b);
        long o = (long)(c0 + i) * ldD + colOfs + r0 + tx;
        dh[o] = a; dl[o] = b;
    }
}

// ---------------- LN forward -> g planes ----------------
__global__ void ln_forward(const float* __restrict__ x,
                           const float* __restrict__ gamma,
                           const float* __restrict__ delta,
                           __nv_bfloat16* __restrict__ gh, __nv_bfloat16* __restrict__ gl,
                           float* __restrict__ rstd_o, float* __restrict__ mean_o) {
    int row = blockIdx.x;
    const float* xr = x + (long)row * D_MODEL;
    int t = threadIdx.x;
    float v[3]; float s = 0.f;
    #pragma unroll
    for (int i = 0; i < 3; i++) { v[i] = xr[t + i*256]; s += v[i]; }
    s = blkSum(s);
    __shared__ float shm, shr;
    if (t == 0) shm = s * (1.0f / D_MODEL);
    __syncthreads();
    float mean = shm;
    float q = 0.f;
    #pragma unroll
    for (int i = 0; i < 3; i++) { float d = v[i] - mean; q += d*d; }
    q = blkSum(q);
    if (t == 0) shr = rsqrtf(q * (1.0f / D_MODEL) + EPS_F);
    __syncthreads();
    float rstd = shr;
    float gm = gamma[0];
    long base = (long)row * D_MODEL;
    #pragma unroll
    for (int i = 0; i < 3; i++) {
        float g = gm * (v[i] - mean) * rstd + delta[t + i*256];
        __nv_bfloat16 a, b; split_val(g, a, b);
        gh[base + t + i*256] = a;
        gl[base + t + i*256] = b;
    }
    if (t == 0) { rstd_o[row] = rstd; mean_o[row] = mean; }
}

// ---------------- fused softmax + split ----------------
__global__ void softmax_split(const float* __restrict__ A,
                              __nv_bfloat16* __restrict__ ph, __nv_bfloat16* __restrict__ pl) {
    long row = blockIdx.x;
    const float4* ar = (const float4*)(A + row * SS);
    int t = threadIdx.x;
    float4 v = ar[t];
    float m = fmaxf(fmaxf(v.x, v.y), fmaxf(v.z, v.w));
    m = blkMax(m);
    __shared__ float shm, shi;
    if (t == 0) shm = m;
    __syncthreads();
    m = shm;
    float e0 = __expf(v.x - m), e1 = __expf(v.y - m);
    float e2 = __expf(v.z - m), e3 = __expf(v.w - m);
    float s = (e0 + e1) + (e2 + e3);
    s = blkSum(s);
    if (t == 0) shi = 1.0f / s;
    __syncthreads();
    float inv = shi;
    long o = row * SS + t * 4;
    float p[4] = { e0*inv, e1*inv, e2*inv, e3*inv };
    #pragma unroll
    for (int i = 0; i < 4; i++) {
        __nv_bfloat16 a, b; split_val(p[i], a, b);
        ph[o + i] = a; pl[o + i] = b;
    }
}

// ---------------- fused LN-backward + SGD update ----------------
__global__ void update_kernel(float* __restrict__ x,
                              const float* __restrict__ ga,
                              const float* __restrict__ gh,
                              const float* __restrict__ gamma,
                              const float* __restrict__ mean_a,
                              const float* __restrict__ rstd_a) {
    int row = blockIdx.x;
    long base = (long)row * D_MODEL;
    int t = threadIdx.x;
    float mean = mean_a[row], rstd = rstd_a[row];
    float xv[3], uv[3], gv[3];
    float s1 = 0.f, s2 = 0.f;
    #pragma unroll
    for (int i = 0; i < 3; i++) {
        long idx = base + t + i*256;
        xv[i] = x[idx];
        uv[i] = xv[i] - ga[idx] - gh[idx];
        gv[i] = (xv[i] - mean) * rstd;
        s1 += uv[i]; s2 += uv[i] * gv[i];
    }
    s1 = blkSum(s1);
    __shared__ float sh1, sh2;
    if (t == 0) sh1 = s1;
    s2 = blkSum(s2);
    if (t == 0) sh2 = s2;
    __syncthreads();
    float mu = sh1 * (1.0f / D_MODEL);
    float mg = sh2 * (1.0f / D_MODEL);
    float gm = gamma[0];
    #pragma unroll
    for (int i = 0; i < 3; i++) {
        float grad = gm * rstd * (uv[i] - mu - gv[i] * mg);
        x[base + t + i*256] = xv[i] - ALPHA_F * grad;
    }
}

// ---------------- mma.sync bf16 split-emulated GEMM ----------------
// C[m,n] = sum_k (Ah+Al)[m,k]*(Bh+Bl)[n,k]    (lo*lo dropped)
// TRA/TRB: 0 -> operand gmem [row][k] K-major ; 1 -> gmem [k][row]
// EPI: 0 fp32 | 1 fp32*beta[zh] | 2 split planes | 3 relu+split planes
template<int BN, int TRA, int TRB, int EPI>
__global__ void __launch_bounds__(256)
mma_gemm(const __nv_bfloat16* __restrict__ Ah, const __nv_bfloat16* __restrict__ Al,
         int lda, long sAb, long sAh,
         const __nv_bfloat16* __restrict__ Bh, const __nv_bfloat16* __restrict__ Bl,
         int ldb, long sBb, long sBh,
         float* __restrict__ C,
         __nv_bfloat16* __restrict__ Ch, __nv_bfloat16* __restrict__ Cl,
         int ldc, long sCb, long sCh,
         int K, const float* __restrict__ betaP) {
    constexpr int BM = 128, BK = 32, SA = 40;            // SA: padded smem row stride (halfs)
    constexpr int WN = (BN == 128) ? 4 : 2;              // warps along n
    constexpr int WM = 8 / WN;                            // warps along m
    constexpr int WTM = BM / WM;                          // 64 or 32
    constexpr int MA = WTM / 16;                          // m-atoms per warp
    constexpr int NA = 4;                                 // 32/8 n-atoms per warp
    constexpr int AH_ = BM * SA;                          // plane halfs
    constexpr int BH_ = BN * SA;
    constexpr int STG = 2*AH_ + 2*BH_;                    // stage halfs
    constexpr bool PIPE = (TRA == 0 && TRB == 0);

    extern __shared__ __nv_bfloat16 smh[];

    int tid = threadIdx.x;
    int wid = tid >> 5, lane = tid & 31;
    int g = lane >> 2, tig = lane & 3;
    int wm = wid % WM, wn = wid / WM;

    int zb = blockIdx.z / N_HEADS, zh = blockIdx.z % N_HEADS;
    const __nv_bfloat16* pAh = Ah + (long)zb * sAb + (long)zh * sAh;
    const __nv_bfloat16* pAl = Al + (long)zb * sAb + (long)zh * sAh;
    const __nv_bfloat16* pBh = Bh + (long)zb * sBb + (long)zh * sBh;
    const __nv_bfloat16* pBl = Bl + (long)zb * sBb + (long)zh * sBh;
    long cOff = (long)zb * sCb + (long)zh * sCh;
    int bm = blockIdx.y * BM, bn = blockIdx.x * BN;

    float acc[MA][NA][4];
    #pragma unroll
    for (int i = 0; i < MA; i++)
        #pragma unroll
        for (int j = 0; j < NA; j++)
            #pragma unroll
            for (int e = 0; e < 4; e++) acc[i][j][e] = 0.f;

    // ---- tile loaders ----
    auto load_nt_async = [&](__nv_bfloat16* sd, const __nv_bfloat16* gp, int ld,
                             int k0, int rbase, int rows) {
        int nch = rows * 4;                                // 16B chunks
        for (int j = 0; j < nch; j += 256) {
            int id = tid + j;
            int r = id >> 2, sg = id & 3;
            cp16(smem_u32(sd + r*SA + sg*8), gp + (long)(rbase + r)*ld + k0 + sg*8);
        }
    };
    auto load_nt_sync = [&](__nv_bfloat16* sd, const __nv_bfloat16* gp, int ld,
                            int k0, int rbase, int rows) {
        int nch = rows * 4;
        for (int j = 0; j < nch; j += 256) {
            int id = tid + j;
            int r = id >> 2, sg = id & 3;
            *(uint4*)(sd + r*SA + sg*8) = *(const uint4*)(gp + (long)(rbase + r)*ld + k0 + sg*8);
        }
    };
    auto load_tr_sync = [&](__nv_bfloat16* sd, const __nv_bfloat16* gp, int ld,
                            int k0, int rbase, int rows) {
        int tot = rows * BK;
        for (int j = 0; j < tot; j += 256) {
            int id = tid + j;
            int m = id % rows, kk = id / rows;
            sd[m*SA + kk] = gp[(long)(k0 + kk)*ld + rbase + m];
        }
    };

    auto compute = [&](const __nv_bfloat16* As_, const __nv_bfloat16* Al_,
                       const __nv_bfloat16* Bs_, const __nv_bfloat16* Bl_) {
        #pragma unroll
        for (int ks = 0; ks < 2; ks++) {
            int ko = ks * 16;
            uint32_t bhf[NA][2], blf[NA][2];
            #pragma unroll
            for (int na = 0; na < NA; na++) {
                int n = wn*32 + na*8 + g;
                bhf[na][0] = lds32(Bs_ + n*SA + ko + tig*2);
                bhf[na][1] = lds32(Bs_ + n*SA + ko + 8 + tig*2);
                blf[na][0] = lds32(Bl_ + n*SA + ko + tig*2);
                blf[na][1] = lds32(Bl_ + n*SA + ko + 8 + tig*2);
            }
            #pragma unroll
            for (int ma = 0; ma < MA; ma++) {
                int r = wm*WTM + ma*16 + g;
                uint32_t ahf[4] = {
                    lds32(As_ + r*SA + ko + tig*2),
                    lds32(As_ + (r+8)*SA + ko + tig*2),
                    lds32(As_ + r*SA + ko + 8 + tig*2),
                    lds32(As_ + (r+8)*SA + ko + 8 + tig*2) };
                uint32_t alf[4] = {
                    lds32(Al_ + r*SA + ko + tig*2),
                    lds32(Al_ + (r+8)*SA + ko + tig*2),
                    lds32(Al_ + r*SA + ko + 8 + tig*2),
                    lds32(Al_ + (r+8)*SA + ko + 8 + tig*2) };
                #pragma unroll
                for (int na = 0; na < NA; na++) {
                    MMA16816(acc[ma][na], ahf, bhf[na]);
                    MMA16816(acc[ma][na], ahf, blf[na]);
                    MMA16816(acc[ma][na], alf, bhf[na]);
                }
            }
        }
    };

    int nCh = K >> 5;
    if (PIPE) {
        // stage 0 prefetch
        load_nt_async(smh,            pAh, lda, 0, bm, BM);
        load_nt_async(smh + AH_,      pAl, lda, 0, bm, BM);
        load_nt_async(smh + 2*AH_,        pBh, ldb, 0, bn, BN);
        load_nt_async(smh + 2*AH_ + BH_,  pBl, ldb, 0, bn, BN);
        cp_commit();
        for (int c = 0; c < nCh; c++) {
            __nv_bfloat16* cur = smh + (c & 1) * STG;
            if (c + 1 < nCh) {
                __nv_bfloat16* nxt = smh + ((c + 1) & 1) * STG;
                int k0 = (c + 1) << 5;
                load_nt_async(nxt,            pAh, lda, k0, bm, BM);
                load_nt_async(nxt + AH_,      pAl, lda, k0, bm, BM);
                load_nt_async(nxt + 2*AH_,        pBh, ldb, k0, bn, BN);
                load_nt_async(nxt + 2*AH_ + BH_,  pBl, ldb, k0, bn, BN);
                cp_commit();
                cp_wait<1>();
            } else {
                cp_wait<0>();
            }
            __syncthreads();
            compute(cur, cur + AH_, cur + 2*AH_, cur + 2*AH_ + BH_);
            __syncthreads();
        }
    } else {
        for (int c = 0; c < nCh; c++) {
            int k0 = c << 5;
            if (TRA == 0) { load_nt_sync(smh, pAh, lda, k0, bm, BM);
                            load_nt_sync(smh + AH_, pAl, lda, k0, bm, BM); }
            else          { load_tr_sync(smh, pAh, lda, k0, bm, BM);
                            load_tr_sync(smh + AH_, pAl, lda, k0, bm, BM); }
            if (TRB == 0) { load_nt_sync(smh + 2*AH_, pBh, ldb, k0, bn, BN);
                            load_nt_sync(smh + 2*AH_ + BH_, pBl, ldb, k0, bn, BN); }
            else          { load_tr_sync(smh + 2*AH_, pBh, ldb, k0, bn, BN);
                            load_tr_sync(smh + 2*AH_ + BH_, pBl, ldb, k0, bn, BN); }
            __syncthreads();
            compute(smh, smh + AH_, smh + 2*AH_, smh + 2*AH_ + BH_);
            __syncthreads();
        }
    }

    // ---- epilogue (direct from registers) ----
    float scale = (EPI == 1) ? betaP[zh] : 1.0f;
    #pragma unroll
    for (int ma = 0; ma < MA; ma++) {
        #pragma unroll
        for (int na = 0; na < NA; na++) {
            int r = bm + wm*WTM + ma*16 + g;
            int cc = bn + wn*32 + na*8 + tig*2;
            if (EPI <= 1) {
                float2 v0 = { acc[ma][na][0]*scale, acc[ma][na][1]*scale };
                float2 v1 = { acc[ma][na][2]*scale, acc[ma][na][3]*scale };
                *(float2*)(C + cOff + (long)r*ldc + cc) = v0;
                *(float2*)(C + cOff + (long)(r+8)*ldc + cc) = v1;
            } else {
                float v0 = acc[ma][na][0], v1 = acc[ma][na][1];
                float v2 = acc[ma][na][2], v3 = acc[ma][na][3];
                if (EPI == 3) { v0 = fmaxf(v0,0.f); v1 = fmaxf(v1,0.f);
                                v2 = fmaxf(v2,0.f); v3 = fmaxf(v3,0.f); }
                __nv_bfloat16 h0,l0,h1,l1,h2,l2,h3,l3;
                split_val(v0,h0,l0); split_val(v1,h1,l1);
                split_val(v2,h2,l2); split_val(v3,h3,l3);
                __nv_bfloat162 th, tl;
                long o0 = cOff + (long)r*ldc + cc;
                long o1 = cOff + (long)(r+8)*ldc + cc;
                th.x = h0; th.y = h1; tl.x = l0; tl.y = l1;
                *(__nv_bfloat162*)(Ch + o0) = th;
                *(__nv_bfloat162*)(Cl + o0) = tl;
                th.x = h2; th.y = h3; tl.x = l2; tl.y = l3;
                *(__nv_bfloat162*)(Ch + o1) = th;
                *(__nv_bfloat162*)(Cl + o1) = tl;
            }
        }
    }
}

// ---------------- driver ----------------
extern "C" void kernel_launch(void* const* d_in, const int* in_sizes, int n_in,
                              void* d_out, int out_size) {
    const float* x_in  = (const float*)d_in[0];
    const float* gamma = (const float*)d_in[1];
    const float* delta = (const float*)d_in[2];
    const float* Wq    = (const float*)d_in[3];
    const float* Wk    = (const float*)d_in[4];
    const float* beta  = (const float*)d_in[5];
    const float* xi    = (const float*)d_in[6];
    float* x = (float*)d_out;

    __nv_bfloat16* bh = nullptr; float* fp = nullptr;
    cudaGetSymbolAddress((void**)&bh, g_bh);
    cudaGetSymbolAddress((void**)&fp, g_fp);

    __nv_bfloat16 *GH = bh+O_GH, *GL = bh+O_GL, *QKH = bh+O_QKH, *QKL = bh+O_QKL;
    __nv_bfloat16 *PH = bh+O_PH, *PL = bh+O_PL, *AQH = bh+O_AQH, *AQL = bh+O_AQL;
    __nv_bfloat16 *HH = bh+O_HH, *HL = bh+O_HL, *WH = bh+O_WH, *WL = bh+O_WL;
    __nv_bfloat16 *WTH = bh+O_WTH, *WTL = bh+O_WTL, *XH = bh+O_XH, *XL = bh+O_XL;
    __nv_bfloat16 *XTH = bh+O_XTH, *XTL = bh+O_XTL;
    float *Abuf = fp+F_A, *Gattn = fp+F_GA, *Ghop = fp+F_GO;
    float *meanb = fp+F_MEAN, *rstd = fp+F_RSTD;

    // smem: stage halfs = 2*128*40 + 2*BN*40 ; bytes x2 stages for PIPE
    constexpr int SM128 = 2 * (2*128*40 + 2*128*40) * 2;   // 81920 B (two stages)
    constexpr int SM64  = (2*128*40 + 2*64*40) * 2;        // 30720 B (one stage)
    cudaFuncSetAttribute(mma_gemm<128,0,0,0>, cudaFuncAttributeMaxDynamicSharedMemorySize, SM128);
    cudaFuncSetAttribute(mma_gemm<128,0,0,1>, cudaFuncAttributeMaxDynamicSharedMemorySize, SM128);
    cudaFuncSetAttribute(mma_gemm<128,0,0,2>, cudaFuncAttributeMaxDynamicSharedMemorySize, SM128);
    cudaFuncSetAttribute(mma_gemm<128,0,0,3>, cudaFuncAttributeMaxDynamicSharedMemorySize, SM128);
    cudaFuncSetAttribute(mma_gemm<64,0,1,2>,  cudaFuncAttributeMaxDynamicSharedMemorySize, SM64);
    cudaFuncSetAttribute(mma_gemm<64,1,1,2>,  cudaFuncAttributeMaxDynamicSharedMemorySize, SM64);

    // ---- setup (constant across steps) ----
    cudaMemcpyAsync(x, x_in, sizeof(float) * NG, cudaMemcpyDeviceToDevice);
    split_mat<<<2304, 256>>>(Wq, WH, WL);
    split_mat<<<2304, 256>>>(Wk, WH + 768*768, WL + 768*768);
    split_mat<<<9216, 256>>>(xi, XH, XL);
    transpose_split<<<dim3(24,24), dim3(32,8)>>>(Wq, 768, 768, WTH, WTL, 1536, 0);
    transpose_split<<<dim3(24,24), dim3(32,8)>>>(Wk, 768, 768, WTH, WTL, 1536, 768);
    transpose_split<<<dim3(24,96), dim3(32,8)>>>(xi, 3072, 768, XTH, XTL, 3072, 0);

    const long sQb = 1024L * 1536;
    const long sPz = (long)SS * SS;

    for (int step = 0; step < NSTEPS; step++) {
        // 1. LN forward -> g planes
        ln_forward<<<ROWS, 256>>>(x, gamma, delta, GH, GL, rstd, meanb);

        // 2. QK = g @ Wqk^T  (8192x1536, K=768)
        mma_gemm<128,0,0,2><<<dim3(12,64,1), 256, SM128>>>(
            GH, GL, 768, 0, 0, WH, WL, 768, 0, 0,
            nullptr, QKH, QKL, 1536, 0, 0, 768, nullptr);

        // 3. scores = beta_h * Q K^T  (96 x 1024x1024, K=64)
        mma_gemm<128,0,0,1><<<dim3(8,8,ZB), 256, SM128>>>(
            QKH, QKL, 1536, sQb, 64,
            QKH + 768, QKL + 768, 1536, sQb, 64,
            Abuf, nullptr, nullptr, SS, (long)N_HEADS * sPz, sPz, 64, beta);

        // 4. fused softmax + split -> P planes
        softmax_split<<<ZB * SS, 256>>>(Abuf, PH, PL);

        // 5. Aq = P @ K  (per z: 1024x64, K=1024)
        mma_gemm<64,0,1,2><<<dim3(1,8,ZB), 256, SM64>>>(
            PH, PL, SS, (long)N_HEADS * sPz, sPz,
            QKH + 768, QKL + 768, 1536, sQb, 64,
            nullptr, AQH, AQL, 1536, sQb, 64, SS, nullptr);

        // 6. Ak = P^T @ Q
        mma_gemm<64,1,1,2><<<dim3(1,8,ZB), 256, SM64>>>(
            PH, PL, SS, (long)N_HEADS * sPz, sPz,
            QKH, QKL, 1536, sQb, 64,
            nullptr, AQH + 768, AQL + 768, 1536, sQb, 64, SS, nullptr);

        // 7. Gattn = AqAk @ Wqk  (8192x768, K=1536)
        mma_gemm<128,0,0,0><<<dim3(6,64,1), 256, SM128>>>(
            AQH, AQL, 1536, 0, 0, WTH, WTL, 1536, 0, 0,
            Gattn, nullptr, nullptr, 768, 0, 0, 1536, nullptr);

        // 8. H = relu(g @ xi^T)  (8192x3072, K=768)
        mma_gemm<128,0,0,3><<<dim3(24,64,1), 256, SM128>>>(
            GH, GL, 768, 0, 0, XH, XL, 768, 0, 0,
            nullptr, HH, HL, 3072, 0, 0, 768, nullptr);

        // 9. Ghop = relu(H) @ xi  (8192x768, K=3072)
        mma_gemm<128,0,0,0><<<dim3(6,64,1), 256, SM128>>>(
            HH, HL, 3072, 0, 0, XTH, XTL, 3072, 0, 0,
            Ghop, nullptr, nullptr, 768, 0, 0, 3072, nullptr);

        // 10. LN backward + SGD update
        update_kernel<<<ROWS, 256>>>(x, Gattn, Ghop, gamma, meanb, rstd);
    }
}

// round 7
// speedup vs baseline: 4.1855x; 1.7573x over previous
#include <cuda_runtime.h>
#include <cuda_bf16.h>
#include <math.h>
#include <stdint.h>

// ---------------- problem constants ----------------
#define D_MODEL 768
#define N_HEADS 12
#define D_HEAD  64
#define N_MEM   3072
#define BB      8
#define SS      1024
#define ROWS    (BB*SS)        // 8192
#define ZB      (BB*N_HEADS)   // 96
#define ALPHA_F 0.1f
#define EPS_F   1e-5f
#define NSTEPS  12

// ---------------- element counts ----------------
constexpr long NG  = (long)ROWS * D_MODEL;
constexpr long NQK = (long)ROWS * 1536;
constexpr long NP  = (long)ZB * SS * SS;
constexpr long NH  = (long)ROWS * N_MEM;
constexpr long NW  = 1536L * 768;
constexpr long NXI = 3072L * 768;

// bf16 plane pool offsets (P and H are single-plane now)
constexpr long O_GH  = 0;            constexpr long O_GL  = O_GH  + NG;
constexpr long O_QKH = O_GL  + NG;   constexpr long O_QKL = O_QKH + NQK;
constexpr long O_PH  = O_QKL + NQK;
constexpr long O_AQH = O_PH  + NP;   constexpr long O_AQL = O_AQH + NQK;
constexpr long O_HH  = O_AQL + NQK;
constexpr long O_WH  = O_HH  + NH;   constexpr long O_WL  = O_WH  + NW;
constexpr long O_WTH = O_WL  + NW;   constexpr long O_WTL = O_WTH + NW;
constexpr long O_XH  = O_WTL + NW;   constexpr long O_XL  = O_XH  + NXI;
constexpr long O_XTH = O_XL  + NXI;  constexpr long O_XTL = O_XTH + NXI;
constexpr long TOT_B = O_XTL + NXI;

// fp32 pool offsets
constexpr long F_A    = 0;
constexpr long F_GA   = F_A  + NP;
constexpr long F_GO   = F_GA + NG;
constexpr long F_MEAN = F_GO + NG;
constexpr long F_RSTD = F_MEAN + ROWS;
constexpr long TOT_F  = F_RSTD + ROWS;

__device__ __align__(256) __nv_bfloat16 g_bh[TOT_B];
__device__ __align__(256) float g_fp[TOT_F];

// ---------------- PTX helpers ----------------
__device__ __forceinline__ uint32_t smem_u32(const void* p) {
    uint32_t a;
    asm("{ .reg .u64 t; cvta.to.shared.u64 t, %1; cvt.u32.u64 %0, t; }" : "=r"(a) : "l"(p));
    return a;
}
__device__ __forceinline__ void cp16(uint32_t dst, const void* src) {
    asm volatile("cp.async.cg.shared.global [%0], [%1], 16;" :: "r"(dst), "l"(src));
}
__device__ __forceinline__ void cp_commit() {
    asm volatile("cp.async.commit_group;" ::: "memory");
}
template<int N> __device__ __forceinline__ void cp_wait() {
    asm volatile("cp.async.wait_group %0;" :: "n"(N) : "memory");
}
__device__ __forceinline__ void ldsm4(uint32_t* r, uint32_t a) {
    asm volatile("ldmatrix.sync.aligned.m8n8.x4.shared.b16 {%0,%1,%2,%3}, [%4];"
        : "=r"(r[0]), "=r"(r[1]), "=r"(r[2]), "=r"(r[3]) : "r"(a));
}
__device__ __forceinline__ void ldsm4t(uint32_t* r, uint32_t a) {
    asm volatile("ldmatrix.sync.aligned.m8n8.x4.trans.shared.b16 {%0,%1,%2,%3}, [%4];"
        : "=r"(r[0]), "=r"(r[1]), "=r"(r[2]), "=r"(r[3]) : "r"(a));
}
#define MMA16816(c, a, b) \
    asm volatile("mma.sync.aligned.m16n8k16.row.col.f32.bf16.bf16.f32 " \
        "{%0,%1,%2,%3}, {%4,%5,%6,%7}, {%8,%9}, {%0,%1,%2,%3};" \
        : "+f"(c[0]), "+f"(c[1]), "+f"(c[2]), "+f"(c[3]) \
        : "r"(a[0]), "r"(a[1]), "r"(a[2]), "r"(a[3]), "r"(b[0]), "r"(b[1]))

__device__ __forceinline__ void split_val(float v, __nv_bfloat16& h, __nv_bfloat16& l) {
    h = __float2bfloat16_rn(v);
    l = __float2bfloat16_rn(v - __bfloat162float(h));
}

// ---------------- reductions ----------------
__device__ __forceinline__ float warpSum(float v) {
    #pragma unroll
    for (int o = 16; o > 0; o >>= 1) v += __shfl_xor_sync(0xffffffffu, v, o);
    return v;
}
__device__ __forceinline__ float warpMax(float v) {
    #pragma unroll
    for (int o = 16; o > 0; o >>= 1) v = fmaxf(v, __shfl_xor_sync(0xffffffffu, v, o));
    return v;
}
__device__ __forceinline__ float blkSum(float v) {
    __shared__ float sh[32];
    int lane = threadIdx.x & 31, wid = threadIdx.x >> 5;
    __syncthreads();
    v = warpSum(v);
    if (lane == 0) sh[wid] = v;
    __syncthreads();
    int nw = (blockDim.x + 31) >> 5;
    v = (threadIdx.x < nw) ? sh[threadIdx.x] : 0.f;
    if (wid == 0) v = warpSum(v);
    return v;
}
__device__ __forceinline__ float blkMax(float v) {
    __shared__ float sh[32];
    int lane = threadIdx.x & 31, wid = threadIdx.x >> 5;
    __syncthreads();
    v = warpMax(v);
    if (lane == 0) sh[wid] = v;
    __syncthreads();
    int nw = (blockDim.x + 31) >> 5;
    v = (threadIdx.x < nw) ? sh[threadIdx.x] : -3.4e38f;
    if (wid == 0) v = warpMax(v);
    return v;
}

// ---------------- prep kernels ----------------
__global__ void split_mat(const float* __restrict__ src,
                          __nv_bfloat16* __restrict__ h, __nv_bfloat16* __restrict__ l) {
    long i = (long)blockIdx.x * 256 + threadIdx.x;
    __nv_bfloat16 a, b; split_val(src[i], a, b);
    h[i] = a; l[i] = b;
}
__global__ void transpose_split(const float* __restrict__ src, int R, int C,
                                __nv_bfloat16* __restrict__ dh, __nv_bfloat16* __restrict__ dl,
                                int ldD, int colOfs) {
    __shared__ float t[32][33];
    int c0 = blockIdx.x * 32, r0 = blockIdx.y * 32;
    int tx = threadIdx.x, ty = threadIdx.y;
    #pragma unroll
    for (int i = ty; i < 32; i += 8)
        t[i][tx] = src[(long)(r0 + i) * C + c0 + tx];
    __syncthreads();
    #pragma unroll
    for (int i = ty; i < 32; i += 8) {
        __nv_bfloat16 a, b; split_val(t[tx][i], a, b);
        long o = (long)(c0 + i) * ldD + colOfs + r0 + tx;
        dh[o] = a; dl[o] = b;
    }
}

// ---------------- LN forward -> g planes ----------------
__global__ void ln_forward(const float* __restrict__ x,
                           const float* __restrict__ gamma,
                           const float* __restrict__ delta,
                           __nv_bfloat16* __restrict__ gh, __nv_bfloat16* __restrict__ gl,
                           float* __restrict__ rstd_o, float* __restrict__ mean_o) {
    int row = blockIdx.x;
    const float* xr = x + (long)row * D_MODEL;
    int t = threadIdx.x;
    float v[3]; float s = 0.f;
    #pragma unroll
    for (int i = 0; i < 3; i++) { v[i] = xr[t + i*256]; s += v[i]; }
    s = blkSum(s);
    __shared__ float shm, shr;
    if (t == 0) shm = s * (1.0f / D_MODEL);
    __syncthreads();
    float mean = shm;
    float q = 0.f;
    #pragma unroll
    for (int i = 0; i < 3; i++) { float d = v[i] - mean; q += d*d; }
    q = blkSum(q);
    if (t == 0) shr = rsqrtf(q * (1.0f / D_MODEL) + EPS_F);
    __syncthreads();
    float rstd = shr;
    float gm = gamma[0];
    long base = (long)row * D_MODEL;
    #pragma unroll
    for (int i = 0; i < 3; i++) {
        float g = gm * (v[i] - mean) * rstd + delta[t + i*256];
        __nv_bfloat16 a, b; split_val(g, a, b);
        gh[base + t + i*256] = a;
        gl[base + t + i*256] = b;
    }
    if (t == 0) { rstd_o[row] = rstd; mean_o[row] = mean; }
}

// ---------------- fused softmax -> single bf16 P plane ----------------
__global__ void softmax_split(const float* __restrict__ A,
                              __nv_bfloat16* __restrict__ ph) {
    long row = blockIdx.x;
    const float4* ar = (const float4*)(A + row * SS);
    int t = threadIdx.x;
    float4 v = ar[t];
    float m = fmaxf(fmaxf(v.x, v.y), fmaxf(v.z, v.w));
    m = blkMax(m);
    __shared__ float shm, shi;
    if (t == 0) shm = m;
    __syncthreads();
    m = shm;
    float e0 = __expf(v.x - m), e1 = __expf(v.y - m);
    float e2 = __expf(v.z - m), e3 = __expf(v.w - m);
    float s = (e0 + e1) + (e2 + e3);
    s = blkSum(s);
    if (t == 0) shi = 1.0f / s;
    __syncthreads();
    float inv = shi;
    __nv_bfloat162* po = (__nv_bfloat162*)(ph + row * SS + t * 4);
    po[0] = __nv_bfloat162{ __float2bfloat16_rn(e0*inv), __float2bfloat16_rn(e1*inv) };
    po[1] = __nv_bfloat162{ __float2bfloat16_rn(e2*inv), __float2bfloat16_rn(e3*inv) };
}

// ---------------- fused LN-backward + SGD update ----------------
__global__ void update_kernel(float* __restrict__ x,
                              const float* __restrict__ ga,
                              const float* __restrict__ gh,
                              const float* __restrict__ gamma,
                              const float* __restrict__ mean_a,
                              const float* __restrict__ rstd_a) {
    int row = blockIdx.x;
    long base = (long)row * D_MODEL;
    int t = threadIdx.x;
    float mean = mean_a[row], rstd = rstd_a[row];
    float xv[3], uv[3], gv[3];
    float s1 = 0.f, s2 = 0.f;
    #pragma unroll
    for (int i = 0; i < 3; i++) {
        long idx = base + t + i*256;
        xv[i] = x[idx];
        uv[i] = xv[i] - ga[idx] - gh[idx];
        gv[i] = (xv[i] - mean) * rstd;
        s1 += uv[i]; s2 += uv[i] * gv[i];
    }
    s1 = blkSum(s1);
    __shared__ float sh1, sh2;
    if (t == 0) sh1 = s1;
    s2 = blkSum(s2);
    if (t == 0) sh2 = s2;
    __syncthreads();
    float mu = sh1 * (1.0f / D_MODEL);
    float mg = sh2 * (1.0f / D_MODEL);
    float gm = gamma[0];
    #pragma unroll
    for (int i = 0; i < 3; i++) {
        float grad = gm * rstd * (uv[i] - mu - gv[i] * mg);
        x[base + t + i*256] = xv[i] - ALPHA_F * grad;
    }
}

// ---------------- mma.sync bf16 split-emulated GEMM (all-pipelined) ----------------
// C[m,n] = sum_k A[m,k]*B[n,k]; A = Ah(+Al if NPROD==3), B = Bh+Bl always.
// AMODE/BMODE: 0 -> gmem [row][k] K-major (normal ldmatrix)
//              2 -> gmem [k][row]        (smem [k][row] + ldmatrix.trans)
// EPI: 0 fp32 | 1 fp32*beta[zh] | 2 split planes | 3 relu+split | 4 relu + hi only
template<int BN, int AMODE, int BMODE, int NPROD, int EPI>
__global__ void __launch_bounds__(256, 2)
mma_gemm(const __nv_bfloat16* __restrict__ Ah, const __nv_bfloat16* __restrict__ Al,
         int lda, long sAb, long sAh,
         const __nv_bfloat16* __restrict__ Bh, const __nv_bfloat16* __restrict__ Bl,
         int ldb, long sBb, long sBh,
         float* __restrict__ C,
         __nv_bfloat16* __restrict__ Ch, __nv_bfloat16* __restrict__ Cl,
         int ldc, long sCb, long sCh,
         int K, const float* __restrict__ betaP) {
    constexpr int BM = 128, BK = 32;
    constexpr int WN = (BN == 128) ? 4 : 2;
    constexpr int WM = 8 / WN;
    constexpr int WTM = BM / WM;                 // 64 or 32
    constexpr int MA = WTM / 16;
    constexpr int NA = 4;
    constexpr int SAn = 40;                      // normal-mode row stride (halfs)
    constexpr int SAtA = BM + 8;                 // trans-mode A stride
    constexpr int SAtB = BN + 8;                 // trans-mode B stride
    constexpr int szA = (AMODE == 0) ? BM * SAn : BK * SAtA;
    constexpr int szB = (BMODE == 0) ? BN * SAn : BK * SAtB;
    constexpr int NAP = (NPROD == 3) ? 2 : 1;
    constexpr int OFF_BH_ = NAP * szA;
    constexpr int OFF_BL_ = OFF_BH_ + szB;
    constexpr int STG = NAP * szA + 2 * szB;

    extern __shared__ __nv_bfloat16 smh[];

    int tid = threadIdx.x;
    int wid = tid >> 5, lane = tid & 31;
    int wm = wid % WM, wn = wid / WM;

    int zb = blockIdx.z / N_HEADS, zh = blockIdx.z % N_HEADS;
    const __nv_bfloat16* pAh = Ah + (long)zb * sAb + (long)zh * sAh;
    const __nv_bfloat16* pAl = (NPROD == 3) ? Al + (long)zb * sAb + (long)zh * sAh : nullptr;
    const __nv_bfloat16* pBh = Bh + (long)zb * sBb + (long)zh * sBh;
    const __nv_bfloat16* pBl = Bl + (long)zb * sBb + (long)zh * sBh;
    long cOff = (long)zb * sCb + (long)zh * sCh;
    int bm = blockIdx.y * BM, bn = blockIdx.x * BN;

    float acc[MA][NA][4];
    #pragma unroll
    for (int i = 0; i < MA; i++)
        #pragma unroll
        for (int j = 0; j < NA; j++)
            #pragma unroll
            for (int e = 0; e < 4; e++) acc[i][j][e] = 0.f;

    // ---- async tile loaders (all 16B chunks) ----
    auto loadA = [&](__nv_bfloat16* sd, const __nv_bfloat16* gp, int k0) {
        if (AMODE == 0) {
            #pragma unroll
            for (int j = 0; j < BM * 4; j += 256) {
                int id = tid + j, r = id >> 2, sg = id & 3;
                cp16(smem_u32(sd + r * SAn + sg * 8), gp + (long)(bm + r) * lda + k0 + sg * 8);
            }
        } else {
            constexpr int CPR = BM / 8;
            #pragma unroll
            for (int j = 0; j < BK * CPR; j += 256) {
                int id = tid + j, kk = id / CPR, sg = id % CPR;
                cp16(smem_u32(sd + kk * SAtA + sg * 8), gp + (long)(k0 + kk) * lda + bm + sg * 8);
            }
        }
    };
    auto loadB = [&](__nv_bfloat16* sd, const __nv_bfloat16* gp, int k0) {
        if (BMODE == 0) {
            #pragma unroll
            for (int j = 0; j < BN * 4; j += 256) {
                int id = tid + j, r = id >> 2, sg = id & 3;
                cp16(smem_u32(sd + r * SAn + sg * 8), gp + (long)(bn + r) * ldb + k0 + sg * 8);
            }
        } else {
            constexpr int CPR = BN / 8;
            #pragma unroll
            for (int j = 0; j < BK * CPR; j += 256) {
                int id = tid + j, kk = id / CPR, sg = id % CPR;
                cp16(smem_u32(sd + kk * SAtB + sg * 8), gp + (long)(k0 + kk) * ldb + bn + sg * 8);
            }
        }
    };
    auto prefetch = [&](__nv_bfloat16* st, int k0) {
        loadA(st, pAh, k0);
        if (NPROD == 3) loadA(st + szA, pAl, k0);
        loadB(st + OFF_BH_, pBh, k0);
        loadB(st + OFF_BL_, pBl, k0);
        cp_commit();
    };

    auto compute = [&](const __nv_bfloat16* cur) {
        const __nv_bfloat16* As_ = cur;
        const __nv_bfloat16* Al_ = cur + szA;
        const __nv_bfloat16* Bs_ = cur + OFF_BH_;
        const __nv_bfloat16* Bl_ = cur + OFF_BL_;
        #pragma unroll
        for (int ks = 0; ks < 2; ks++) {
            int ko = ks * 16;
            uint32_t bhf[NA][2], blf[NA][2];
            #pragma unroll
            for (int pr = 0; pr < 2; pr++) {
                uint32_t r[4], rl[4];
                if (BMODE == 0) {
                    int q = lane >> 3, idx = lane & 7;
                    int nrow = wn * 32 + pr * 16 + (q >> 1) * 8 + idx;
                    int kcol = ko + (q & 1) * 8;
                    ldsm4(r,  smem_u32(Bs_ + nrow * SAn + kcol));
                    ldsm4(rl, smem_u32(Bl_ + nrow * SAn + kcol));
                } else {
                    int krow = ko + ((lane >> 3) & 1) * 8 + (lane & 7);
                    int ncol = wn * 32 + pr * 16 + (lane >> 4) * 8;
                    ldsm4t(r,  smem_u32(Bs_ + krow * SAtB + ncol));
                    ldsm4t(rl, smem_u32(Bl_ + krow * SAtB + ncol));
                }
                bhf[pr*2][0] = r[0];  bhf[pr*2][1] = r[1];
                bhf[pr*2+1][0] = r[2]; bhf[pr*2+1][1] = r[3];
                blf[pr*2][0] = rl[0]; blf[pr*2][1] = rl[1];
                blf[pr*2+1][0] = rl[2]; blf[pr*2+1][1] = rl[3];
            }
            #pragma unroll
            for (int ma = 0; ma < MA; ma++) {
                uint32_t ahf[4], alf[4];
                if (AMODE == 0) {
                    int arow = wm * WTM + ma * 16 + (lane & 15);
                    int akcol = ko + (lane >> 4) * 8;
                    ldsm4(ahf, smem_u32(As_ + arow * SAn + akcol));
                    if (NPROD == 3) ldsm4(alf, smem_u32(Al_ + arow * SAn + akcol));
                } else {
                    int akrow = ko + (lane & 7) + (lane >> 4) * 8;
                    int amcol = wm * WTM + ma * 16 + ((lane >> 3) & 1) * 8;
                    ldsm4t(ahf, smem_u32(As_ + akrow * SAtA + amcol));
                    if (NPROD == 3) ldsm4t(alf, smem_u32(Al_ + akrow * SAtA + amcol));
                }
                #pragma unroll
                for (int na = 0; na < NA; na++) {
                    MMA16816(acc[ma][na], ahf, bhf[na]);
                    MMA16816(acc[ma][na], ahf, blf[na]);
                    if (NPROD == 3) MMA16816(acc[ma][na], alf, bhf[na]);
                }
            }
        }
    };

    int nCh = K >> 5;
    prefetch(smh, 0);
    for (int c = 0; c < nCh; c++) {
        __nv_bfloat16* cur = smh + (c & 1) * STG;
        if (c + 1 < nCh) {
            prefetch(smh + ((c + 1) & 1) * STG, (c + 1) << 5);
            cp_wait<1>();
        } else {
            cp_wait<0>();
        }
        __syncthreads();
        compute(cur);
        __syncthreads();
    }

    // ---- epilogue (direct from registers) ----
    int g = lane >> 2, tig = lane & 3;
    float scale = (EPI == 1) ? betaP[zh] : 1.0f;
    #pragma unroll
    for (int ma = 0; ma < MA; ma++) {
        #pragma unroll
        for (int na = 0; na < NA; na++) {
            int r = bm + wm*WTM + ma*16 + g;
            int cc = bn + wn*32 + na*8 + tig*2;
            if (EPI <= 1) {
                float2 v0 = { acc[ma][na][0]*scale, acc[ma][na][1]*scale };
                float2 v1 = { acc[ma][na][2]*scale, acc[ma][na][3]*scale };
                *(float2*)(C + cOff + (long)r*ldc + cc) = v0;
                *(float2*)(C + cOff + (long)(r+8)*ldc + cc) = v1;
            } else if (EPI == 4) {
                float v0 = fmaxf(acc[ma][na][0], 0.f), v1 = fmaxf(acc[ma][na][1], 0.f);
                float v2 = fmaxf(acc[ma][na][2], 0.f), v3 = fmaxf(acc[ma][na][3], 0.f);
                long o0 = cOff + (long)r*ldc + cc;
                long o1 = cOff + (long)(r+8)*ldc + cc;
                *(__nv_bfloat162*)(Ch + o0) =
                    __nv_bfloat162{ __float2bfloat16_rn(v0), __float2bfloat16_rn(v1) };
                *(__nv_bfloat162*)(Ch + o1) =
                    __nv_bfloat162{ __float2bfloat16_rn(v2), __float2bfloat16_rn(v3) };
            } else {
                float v0 = acc[ma][na][0], v1 = acc[ma][na][1];
                float v2 = acc[ma][na][2], v3 = acc[ma][na][3];
                if (EPI == 3) { v0 = fmaxf(v0,0.f); v1 = fmaxf(v1,0.f);
                                v2 = fmaxf(v2,0.f); v3 = fmaxf(v3,0.f); }
                __nv_bfloat16 h0,l0,h1,l1,h2,l2,h3,l3;
                split_val(v0,h0,l0); split_val(v1,h1,l1);
                split_val(v2,h2,l2); split_val(v3,h3,l3);
                long o0 = cOff + (long)r*ldc + cc;
                long o1 = cOff + (long)(r+8)*ldc + cc;
                *(__nv_bfloat162*)(Ch + o0) = __nv_bfloat162{h0, h1};
                *(__nv_bfloat162*)(Cl + o0) = __nv_bfloat162{l0, l1};
                *(__nv_bfloat162*)(Ch + o1) = __nv_bfloat162{h2, h3};
                *(__nv_bfloat162*)(Cl + o1) = __nv_bfloat162{l2, l3};
            }
        }
    }
}

// ---------------- driver ----------------
extern "C" void kernel_launch(void* const* d_in, const int* in_sizes, int n_in,
                              void* d_out, int out_size) {
    const float* x_in  = (const float*)d_in[0];
    const float* gamma = (const float*)d_in[1];
    const float* delta = (const float*)d_in[2];
    const float* Wq    = (const float*)d_in[3];
    const float* Wk    = (const float*)d_in[4];
    const float* beta  = (const float*)d_in[5];
    const float* xi    = (const float*)d_in[6];
    float* x = (float*)d_out;

    __nv_bfloat16* bh = nullptr; float* fp = nullptr;
    cudaGetSymbolAddress((void**)&bh, g_bh);
    cudaGetSymbolAddress((void**)&fp, g_fp);

    __nv_bfloat16 *GH = bh+O_GH, *GL = bh+O_GL, *QKH = bh+O_QKH, *QKL = bh+O_QKL;
    __nv_bfloat16 *PH = bh+O_PH, *AQH = bh+O_AQH, *AQL = bh+O_AQL;
    __nv_bfloat16 *HH = bh+O_HH, *WH = bh+O_WH, *WL = bh+O_WL;
    __nv_bfloat16 *WTH = bh+O_WTH, *WTL = bh+O_WTL, *XH = bh+O_XH, *XL = bh+O_XL;
    __nv_bfloat16 *XTH = bh+O_XTH, *XTL = bh+O_XTL;
    float *Abuf = fp+F_A, *Gattn = fp+F_GA, *Ghop = fp+F_GO;
    float *meanb = fp+F_MEAN, *rstd = fp+F_RSTD;

    // smem bytes: STG halfs * 2 B * 2 stages
    constexpr int SM_BIG  = (2*128*40 + 2*128*40) * 2 * 2;   // 81920 (NPROD3, 128/0/0)
    constexpr int SM_GHOP = (1*128*40 + 2*128*40) * 2 * 2;   // 61440 (NPROD2, 128/0/0)
    constexpr int SM_AQ   = (1*128*40 + 2*32*72) * 2 * 2;    // 38912 (64, A0 B2, NPROD2)
    constexpr int SM_AK   = (1*32*136 + 2*32*72) * 2 * 2;    // 35840 (64, A2 B2, NPROD2)
    cudaFuncSetAttribute(mma_gemm<128,0,0,3,0>, cudaFuncAttributeMaxDynamicSharedMemorySize, SM_BIG);
    cudaFuncSetAttribute(mma_gemm<128,0,0,3,1>, cudaFuncAttributeMaxDynamicSharedMemorySize, SM_BIG);
    cudaFuncSetAttribute(mma_gemm<128,0,0,3,2>, cudaFuncAttributeMaxDynamicSharedMemorySize, SM_BIG);
    cudaFuncSetAttribute(mma_gemm<128,0,0,3,4>, cudaFuncAttributeMaxDynamicSharedMemorySize, SM_BIG);
    cudaFuncSetAttribute(mma_gemm<128,0,0,2,0>, cudaFuncAttributeMaxDynamicSharedMemorySize, SM_GHOP);

    // ---- setup (constant across steps) ----
    cudaMemcpyAsync(x, x_in, sizeof(float) * NG, cudaMemcpyDeviceToDevice);
    split_mat<<<2304, 256>>>(Wq, WH, WL);
    split_mat<<<2304, 256>>>(Wk, WH + 768*768, WL + 768*768);
    split_mat<<<9216, 256>>>(xi, XH, XL);
    transpose_split<<<dim3(24,24), dim3(32,8)>>>(Wq, 768, 768, WTH, WTL, 1536, 0);
    transpose_split<<<dim3(24,24), dim3(32,8)>>>(Wk, 768, 768, WTH, WTL, 1536, 768);
    transpose_split<<<dim3(24,96), dim3(32,8)>>>(xi, 3072, 768, XTH, XTL, 3072, 0);

    const long sQb = 1024L * 1536;
    const long sPz = (long)SS * SS;

    for (int step = 0; step < NSTEPS; step++) {
        // 1. LN forward -> g planes
        ln_forward<<<ROWS, 256>>>(x, gamma, delta, GH, GL, rstd, meanb);

        // 2. QK = g @ Wqk^T  (8192x1536, K=768)
        mma_gemm<128,0,0,3,2><<<dim3(12,64,1), 256, SM_BIG>>>(
            GH, GL, 768, 0, 0, WH, WL, 768, 0, 0,
            nullptr, QKH, QKL, 1536, 0, 0, 768, nullptr);

        // 3. scores = beta_h * Q K^T  (96 x 1024x1024, K=64)
        mma_gemm<128,0,0,3,1><<<dim3(8,8,ZB), 256, SM_BIG>>>(
            QKH, QKL, 1536, sQb, 64,
            QKH + 768, QKL + 768, 1536, sQb, 64,
            Abuf, nullptr, nullptr, SS, (long)N_HEADS * sPz, sPz, 64, beta);

        // 4. fused softmax -> single P plane
        softmax_split<<<ZB * SS, 256>>>(Abuf, PH);

        // 5. Aq = P @ K  (per z: 1024x64, K=1024); B = K via [k][n]+trans
        mma_gemm<64,0,2,2,2><<<dim3(1,8,ZB), 256, SM_AQ>>>(
            PH, nullptr, SS, (long)N_HEADS * sPz, sPz,
            QKH + 768, QKL + 768, 1536, sQb, 64,
            nullptr, AQH, AQL, 1536, sQb, 64, SS, nullptr);

        // 6. Ak = P^T @ Q  (A = P via [k][m]+trans, B = Q via [k][n]+trans)
        mma_gemm<64,2,2,2,2><<<dim3(1,8,ZB), 256, SM_AK>>>(
            PH, nullptr, SS, (long)N_HEADS * sPz, sPz,
            QKH, QKL, 1536, sQb, 64,
            nullptr, AQH + 768, AQL + 768, 1536, sQb, 64, SS, nullptr);

        // 7. Gattn = AqAk @ Wqk  (8192x768, K=1536)
        mma_gemm<128,0,0,3,0><<<dim3(6,64,1), 256, SM_BIG>>>(
            AQH, AQL, 1536, 0, 0, WTH, WTL, 1536, 0, 0,
            Gattn, nullptr, nullptr, 768, 0, 0, 1536, nullptr);

        // 8. H = relu(g @ xi^T)  (8192x3072, K=768) -> single plane
        mma_gemm<128,0,0,3,4><<<dim3(24,64,1), 256, SM_BIG>>>(
            GH, GL, 768, 0, 0, XH, XL, 768, 0, 0,
            nullptr, HH, nullptr, 3072, 0, 0, 768, nullptr);

        // 9. Ghop = relu(H) @ xi  (8192x768, K=3072); A = H single plane
        mma_gemm<128,0,0,2,0><<<dim3(6,64,1), 256, SM_GHOP>>>(
            HH, nullptr, 3072, 0, 0, XTH, XTL, 3072, 0, 0,
            Ghop, nullptr, nullptr, 768, 0, 0, 3072, nullptr);

        // 10. LN backward + SGD update
        update_kernel<<<ROWS, 256>>>(x, Gattn, Ghop, gamma, meanb, rstd);
    }
}

// round 10
// speedup vs baseline: 4.3833x; 1.0473x over previous
#include <cuda_runtime.h>
#include <cuda_bf16.h>
#include <math.h>
#include <stdint.h>

// ---------------- problem constants ----------------
#define D_MODEL 768
#define N_HEADS 12
#define D_HEAD  64
#define N_MEM   3072
#define BB      8
#define SS      1024
#define ROWS    (BB*SS)        // 8192
#define ZB      (BB*N_HEADS)   // 96
#define ALPHA_F 0.1f
#define EPS_F   1e-5f
#define NSTEPS  12

// ---------------- element counts ----------------
constexpr long NG  = (long)ROWS * D_MODEL;
constexpr long NQK = (long)ROWS * 1536;
constexpr long NP  = (long)ZB * SS * SS;
constexpr long NH  = (long)ROWS * N_MEM;
constexpr long NW  = 1536L * 768;
constexpr long NXI = 3072L * 768;

// bf16 plane pool offsets
constexpr long O_GH  = 0;            constexpr long O_GL  = O_GH  + NG;
constexpr long O_QKH = O_GL  + NG;   constexpr long O_QKL = O_QKH + NQK;
constexpr long O_PH  = O_QKL + NQK;
constexpr long O_AB  = O_PH  + NP;                       // bf16 scores (beta*A)
constexpr long O_AQH = O_AB  + NP;   constexpr long O_AQL = O_AQH + NQK;
constexpr long O_HH  = O_AQL + NQK;
constexpr long O_WH  = O_HH  + NH;   constexpr long O_WL  = O_WH  + NW;
constexpr long O_WTH = O_WL  + NW;   constexpr long O_WTL = O_WTH + NW;
constexpr long O_XH  = O_WTL + NW;   constexpr long O_XL  = O_XH  + NXI;
constexpr long O_XTH = O_XL  + NXI;  constexpr long O_XTL = O_XTH + NXI;
constexpr long TOT_B = O_XTL + NXI;

// fp32 pool offsets
constexpr long F_GA   = 0;
constexpr long F_GO   = F_GA + NG;
constexpr long F_MEAN = F_GO + NG;
constexpr long F_RSTD = F_MEAN + ROWS;
constexpr long TOT_F  = F_RSTD + ROWS;

__device__ __align__(256) __nv_bfloat16 g_bh[TOT_B];
__device__ __align__(256) float g_fp[TOT_F];

// ---------------- PTX helpers ----------------
__device__ __forceinline__ uint32_t smem_u32(const void* p) {
    uint32_t a;
    asm("{ .reg .u64 t; cvta.to.shared.u64 t, %1; cvt.u32.u64 %0, t; }" : "=r"(a) : "l"(p));
    return a;
}
__device__ __forceinline__ void cp16(uint32_t dst, const void* src) {
    asm volatile("cp.async.cg.shared.global [%0], [%1], 16;" :: "r"(dst), "l"(src));
}
__device__ __forceinline__ void cp_commit() {
    asm volatile("cp.async.commit_group;" ::: "memory");
}
template<int N> __device__ __forceinline__ void cp_wait() {
    asm volatile("cp.async.wait_group %0;" :: "n"(N) : "memory");
}
__device__ __forceinline__ void ldsm4(uint32_t* r, uint32_t a) {
    asm volatile("ldmatrix.sync.aligned.m8n8.x4.shared.b16 {%0,%1,%2,%3}, [%4];"
        : "=r"(r[0]), "=r"(r[1]), "=r"(r[2]), "=r"(r[3]) : "r"(a));
}
__device__ __forceinline__ void ldsm4t(uint32_t* r, uint32_t a) {
    asm volatile("ldmatrix.sync.aligned.m8n8.x4.trans.shared.b16 {%0,%1,%2,%3}, [%4];"
        : "=r"(r[0]), "=r"(r[1]), "=r"(r[2]), "=r"(r[3]) : "r"(a));
}
#define MMA16816(c, a, b) \
    asm volatile("mma.sync.aligned.m16n8k16.row.col.f32.bf16.bf16.f32 " \
        "{%0,%1,%2,%3}, {%4,%5,%6,%7}, {%8,%9}, {%0,%1,%2,%3};" \
        : "+f"(c[0]), "+f"(c[1]), "+f"(c[2]), "+f"(c[3]) \
        : "r"(a[0]), "r"(a[1]), "r"(a[2]), "r"(a[3]), "r"(b[0]), "r"(b[1]))

__device__ __forceinline__ void split_val(float v, __nv_bfloat16& h, __nv_bfloat16& l) {
    h = __float2bfloat16_rn(v);
    l = __float2bfloat16_rn(v - __bfloat162float(h));
}

// ---------------- reductions ----------------
__device__ __forceinline__ float warpSum(float v) {
    #pragma unroll
    for (int o = 16; o > 0; o >>= 1) v += __shfl_xor_sync(0xffffffffu, v, o);
    return v;
}
__device__ __forceinline__ float warpMax(float v) {
    #pragma unroll
    for (int o = 16; o > 0; o >>= 1) v = fmaxf(v, __shfl_xor_sync(0xffffffffu, v, o));
    return v;
}
__device__ __forceinline__ float blkSum(float v) {
    __shared__ float sh[32];
    int lane = threadIdx.x & 31, wid = threadIdx.x >> 5;
    __syncthreads();
    v = warpSum(v);
    if (lane == 0) sh[wid] = v;
    __syncthreads();
    int nw = (blockDim.x + 31) >> 5;
    v = (threadIdx.x < nw) ? sh[threadIdx.x] : 0.f;
    if (wid == 0) v = warpSum(v);
    return v;
}
__device__ __forceinline__ float blkMax(float v) {
    __shared__ float sh[32];
    int lane = threadIdx.x & 31, wid = threadIdx.x >> 5;
    __syncthreads();
    v = warpMax(v);
    if (lane == 0) sh[wid] = v;
    __syncthreads();
    int nw = (blockDim.x + 31) >> 5;
    v = (threadIdx.x < nw) ? sh[threadIdx.x] : -3.4e38f;
    if (wid == 0) v = warpMax(v);
    return v;
}

// ---------------- prep kernels ----------------
__global__ void split_mat(const float* __restrict__ src,
                          __nv_bfloat16* __restrict__ h, __nv_bfloat16* __restrict__ l) {
    long i = (long)blockIdx.x * 256 + threadIdx.x;
    __nv_bfloat16 a, b; split_val(src[i], a, b);
    h[i] = a; l[i] = b;
}
__global__ void transpose_split(const float* __restrict__ src, int R, int C,
                                __nv_bfloat16* __restrict__ dh, __nv_bfloat16* __restrict__ dl,
                                int ldD, int colOfs) {
    __shared__ float t[32][33];
    int c0 = blockIdx.x * 32, r0 = blockIdx.y * 32;
    int tx = threadIdx.x, ty = threadIdx.y;
    #pragma unroll
    for (int i = ty; i < 32; i += 8)
        t[i][tx] = src[(long)(r0 + i) * C + c0 + tx];
    __syncthreads();
    #pragma unroll
    for (int i = ty; i < 32; i += 8) {
        __nv_bfloat16 a, b; split_val(t[tx][i], a, b);
        long o = (long)(c0 + i) * ldD + colOfs + r0 + tx;
        dh[o] = a; dl[o] = b;
    }
}

// ---------------- LN forward -> g planes ----------------
__global__ void ln_forward(const float* __restrict__ x,
                           const float* __restrict__ gamma,
                           const float* __restrict__ delta,
                           __nv_bfloat16* __restrict__ gh, __nv_bfloat16* __restrict__ gl,
                           float* __restrict__ rstd_o, float* __restrict__ mean_o) {
    int row = blockIdx.x;
    const float* xr = x + (long)row * D_MODEL;
    int t = threadIdx.x;
    float v[3]; float s = 0.f;
    #pragma unroll
    for (int i = 0; i < 3; i++) { v[i] = xr[t + i*256]; s += v[i]; }
    s = blkSum(s);
    __shared__ float shm, shr;
    if (t == 0) shm = s * (1.0f / D_MODEL);
    __syncthreads();
    float mean = shm;
    float q = 0.f;
    #pragma unroll
    for (int i = 0; i < 3; i++) { float d = v[i] - mean; q += d*d; }
    q = blkSum(q);
    if (t == 0) shr = rsqrtf(q * (1.0f / D_MODEL) + EPS_F);
    __syncthreads();
    float rstd = shr;
    float gm = gamma[0];
    long base = (long)row * D_MODEL;
    #pragma unroll
    for (int i = 0; i < 3; i++) {
        float g = gm * (v[i] - mean) * rstd + delta[t + i*256];
        __nv_bfloat16 a, b; split_val(g, a, b);
        gh[base + t + i*256] = a;
        gl[base + t + i*256] = b;
    }
    if (t == 0) { rstd_o[row] = rstd; mean_o[row] = mean; }
}

// ---------------- fused softmax over bf16 scores -> single bf16 P ----------------
__global__ void softmax_split(const __nv_bfloat16* __restrict__ A,
                              __nv_bfloat16* __restrict__ ph) {
    long row = blockIdx.x;
    const __nv_bfloat162* ar = (const __nv_bfloat162*)(A + row * SS);
    int t = threadIdx.x;
    __nv_bfloat162 b0 = ar[t*2], b1 = ar[t*2+1];
    float v0 = __bfloat162float(b0.x), v1 = __bfloat162float(b0.y);
    float v2 = __bfloat162float(b1.x), v3 = __bfloat162float(b1.y);
    float m = fmaxf(fmaxf(v0, v1), fmaxf(v2, v3));
    m = blkMax(m);
    __shared__ float shm, shi;
    if (t == 0) shm = m;
    __syncthreads();
    m = shm;
    float e0 = __expf(v0 - m), e1 = __expf(v1 - m);
    float e2 = __expf(v2 - m), e3 = __expf(v3 - m);
    float s = (e0 + e1) + (e2 + e3);
    s = blkSum(s);
    if (t == 0) shi = 1.0f / s;
    __syncthreads();
    float inv = shi;
    __nv_bfloat162* po = (__nv_bfloat162*)(ph + row * SS + t * 4);
    po[0] = __nv_bfloat162{ __float2bfloat16_rn(e0*inv), __float2bfloat16_rn(e1*inv) };
    po[1] = __nv_bfloat162{ __float2bfloat16_rn(e2*inv), __float2bfloat16_rn(e3*inv) };
}

// ---------------- fused LN-backward + SGD update ----------------
__global__ void update_kernel(float* __restrict__ x,
                              const float* __restrict__ ga,
                              const float* __restrict__ gh,
                              const float* __restrict__ gamma,
                              const float* __restrict__ mean_a,
                              const float* __restrict__ rstd_a) {
    int row = blockIdx.x;
    long base = (long)row * D_MODEL;
    int t = threadIdx.x;
    float mean = mean_a[row], rstd = rstd_a[row];
    float xv[3], uv[3], gv[3];
    float s1 = 0.f, s2 = 0.f;
    #pragma unroll
    for (int i = 0; i < 3; i++) {
        long idx = base + t + i*256;
        xv[i] = x[idx];
        uv[i] = xv[i] - ga[idx] - gh[idx];
        gv[i] = (xv[i] - mean) * rstd;
        s1 += uv[i]; s2 += uv[i] * gv[i];
    }
    s1 = blkSum(s1);
    __shared__ float sh1, sh2;
    if (t == 0) sh1 = s1;
    s2 = blkSum(s2);
    if (t == 0) sh2 = s2;
    __syncthreads();
    float mu = sh1 * (1.0f / D_MODEL);
    float mg = sh2 * (1.0f / D_MODEL);
    float gm = gamma[0];
    #pragma unroll
    for (int i = 0; i < 3; i++) {
        float grad = gm * rstd * (uv[i] - mu - gv[i] * mg);
        x[base + t + i*256] = xv[i] - ALPHA_F * grad;
    }
}

// ---------------- mma.sync bf16 split-emulated GEMM ----------------
// 128 threads, 4 warps, warp tile 64 x (BN/2). 2-stage cp.async, single sync/chunk.
// C[m,n] = sum_k A[m,k]*B[n,k]; A = Ah(+Al if NPROD==3), B = Bh+Bl.
// AMODE/BMODE: 0 -> gmem [row][k] K-major; 2 -> gmem [k][row] (trans via ldmatrix.trans)
// EPI: 0 fp32 | 2 split planes | 3 relu+split | 4 relu+hi | 5 beta-scaled bf16
template<int BN, int AMODE, int BMODE, int NPROD, int EPI>
__global__ void __launch_bounds__(128)
mma_gemm(const __nv_bfloat16* __restrict__ Ah, const __nv_bfloat16* __restrict__ Al,
         int lda, long sAb, long sAh,
         const __nv_bfloat16* __restrict__ Bh, const __nv_bfloat16* __restrict__ Bl,
         int ldb, long sBb, long sBh,
         float* __restrict__ C,
         __nv_bfloat16* __restrict__ Ch, __nv_bfloat16* __restrict__ Cl,
         int ldc, long sCb, long sCh,
         int K, const float* __restrict__ betaP) {
    constexpr int BM = 128, BK = 32;
    constexpr int WTN = BN / 2;                  // warp n-tile (64 or 32)
    constexpr int MA = 4;                        // 64/16 m-atoms
    constexpr int NA = WTN / 8;                  // 8 or 4 n-atoms
    constexpr int SAn = 40;
    constexpr int SAtA = BM + 8;
    constexpr int SAtB = BN + 8;
    constexpr int szA = (AMODE == 0) ? BM * SAn : BK * SAtA;
    constexpr int szB = (BMODE == 0) ? BN * SAn : BK * SAtB;
    constexpr int NAP = (NPROD == 3) ? 2 : 1;
    constexpr int OFF_BH_ = NAP * szA;
    constexpr int OFF_BL_ = OFF_BH_ + szB;
    constexpr int STG = NAP * szA + 2 * szB;

    extern __shared__ __nv_bfloat16 smh[];

    int tid = threadIdx.x;
    int wid = tid >> 5, lane = tid & 31;
    int wm = wid & 1, wn = wid >> 1;             // WM=2, WN=2

    int zb = blockIdx.z / N_HEADS, zh = blockIdx.z % N_HEADS;
    const __nv_bfloat16* pAh = Ah + (long)zb * sAb + (long)zh * sAh;
    const __nv_bfloat16* pAl = (NPROD == 3) ? Al + (long)zb * sAb + (long)zh * sAh : nullptr;
    const __nv_bfloat16* pBh = Bh + (long)zb * sBb + (long)zh * sBh;
    const __nv_bfloat16* pBl = Bl + (long)zb * sBb + (long)zh * sBh;
    long cOff = (long)zb * sCb + (long)zh * sCh;
    int bm = blockIdx.y * BM, bn = blockIdx.x * BN;

    float acc[MA][NA][4];
    #pragma unroll
    for (int i = 0; i < MA; i++)
        #pragma unroll
        for (int j = 0; j < NA; j++)
            #pragma unroll
            for (int e = 0; e < 4; e++) acc[i][j][e] = 0.f;

    // ---- async tile loaders (128 threads, 16B chunks) ----
    auto loadA = [&](__nv_bfloat16* sd, const __nv_bfloat16* gp, int k0) {
        if (AMODE == 0) {
            #pragma unroll
            for (int j = 0; j < BM * 4; j += 128) {
                int id = tid + j, r = id >> 2, sg = id & 3;
                cp16(smem_u32(sd + r * SAn + sg * 8), gp + (long)(bm + r) * lda + k0 + sg * 8);
            }
        } else {
            constexpr int CPR = BM / 8;
            #pragma unroll
            for (int j = 0; j < BK * CPR; j += 128) {
                int id = tid + j, kk = id / CPR, sg = id % CPR;
                cp16(smem_u32(sd + kk * SAtA + sg * 8), gp + (long)(k0 + kk) * lda + bm + sg * 8);
            }
        }
    };
    auto loadB = [&](__nv_bfloat16* sd, const __nv_bfloat16* gp, int k0) {
        if (BMODE == 0) {
            #pragma unroll
            for (int j = 0; j < BN * 4; j += 128) {
                int id = tid + j, r = id >> 2, sg = id & 3;
                cp16(smem_u32(sd + r * SAn + sg * 8), gp + (long)(bn + r) * ldb + k0 + sg * 8);
            }
        } else {
            constexpr int CPR = BN / 8;
            #pragma unroll
            for (int j = 0; j < BK * CPR; j += 128) {
                int id = tid + j, kk = id / CPR, sg = id % CPR;
                cp16(smem_u32(sd + kk * SAtB + sg * 8), gp + (long)(k0 + kk) * ldb + bn + sg * 8);
            }
        }
    };
    auto prefetch = [&](__nv_bfloat16* st, int k0) {
        loadA(st, pAh, k0);
        if (NPROD == 3) loadA(st + szA, pAl, k0);
        loadB(st + OFF_BH_, pBh, k0);
        loadB(st + OFF_BL_, pBl, k0);
        cp_commit();
    };

    auto compute = [&](const __nv_bfloat16* cur) {
        const __nv_bfloat16* As_ = cur;
        const __nv_bfloat16* Al_ = cur + szA;
        const __nv_bfloat16* Bs_ = cur + OFF_BH_;
        const __nv_bfloat16* Bl_ = cur + OFF_BL_;
        #pragma unroll
        for (int ks = 0; ks < 2; ks++) {
            int ko = ks * 16;
            uint32_t bhf[NA][2], blf[NA][2];
            #pragma unroll
            for (int pr = 0; pr < NA/2; pr++) {
                uint32_t r[4], rl[4];
                if (BMODE == 0) {
                    int q = lane >> 3, idx = lane & 7;
                    int nrow = wn * WTN + pr * 16 + (q >> 1) * 8 + idx;
                    int kcol = ko + (q & 1) * 8;
                    ldsm4(r,  smem_u32(Bs_ + nrow * SAn + kcol));
                    ldsm4(rl, smem_u32(Bl_ + nrow * SAn + kcol));
                } else {
                    int krow = ko + ((lane >> 3) & 1) * 8 + (lane & 7);
                    int ncol = wn * WTN + pr * 16 + (lane >> 4) * 8;
                    ldsm4t(r,  smem_u32(Bs_ + krow * SAtB + ncol));
                    ldsm4t(rl, smem_u32(Bl_ + krow * SAtB + ncol));
                }
                bhf[pr*2][0] = r[0];  bhf[pr*2][1] = r[1];
                bhf[pr*2+1][0] = r[2]; bhf[pr*2+1][1] = r[3];
                blf[pr*2][0] = rl[0]; blf[pr*2][1] = rl[1];
                blf[pr*2+1][0] = rl[2]; blf[pr*2+1][1] = rl[3];
            }
            #pragma unroll
            for (int ma = 0; ma < MA; ma++) {
                uint32_t ahf[4], alf[4];
                if (AMODE == 0) {
                    int arow = wm * 64 + ma * 16 + (lane & 15);
                    int akcol = ko + (lane >> 4) * 8;
                    ldsm4(ahf, smem_u32(As_ + arow * SAn + akcol));
                    if (NPROD == 3) ldsm4(alf, smem_u32(Al_ + arow * SAn + akcol));
                } else {
                    int akrow = ko + (lane & 7) + (lane >> 4) * 8;
                    int amcol = wm * 64 + ma * 16 + ((lane >> 3) & 1) * 8;
                    ldsm4t(ahf, smem_u32(As_ + akrow * SAtA + amcol));
                    if (NPROD == 3) ldsm4t(alf, smem_u32(Al_ + akrow * SAtA + amcol));
                }
                #pragma unroll
                for (int na = 0; na < NA; na++) {
                    MMA16816(acc[ma][na], ahf, bhf[na]);
                    MMA16816(acc[ma][na], ahf, blf[na]);
                    if (NPROD == 3) MMA16816(acc[ma][na], alf, bhf[na]);
                }
            }
        }
    };

    int nCh = K >> 5;
    prefetch(smh, 0);
    for (int c = 0; c < nCh; c++) {
        cp_wait<0>();
        __syncthreads();
        if (c + 1 < nCh) prefetch(smh + ((c + 1) & 1) * STG, (c + 1) << 5);
        compute(smh + (c & 1) * STG);
    }

    // ---- epilogue (direct from registers) ----
    int g = lane >> 2, tig = lane & 3;
    float scale = (EPI == 5) ? betaP[zh] : 1.0f;
    #pragma unroll
    for (int ma = 0; ma < MA; ma++) {
        #pragma unroll
        for (int na = 0; na < NA; na++) {
            int r = bm + wm*64 + ma*16 + g;
            int cc = bn + wn*WTN + na*8 + tig*2;
            long o0 = cOff + (long)r*ldc + cc;
            long o1 = cOff + (long)(r+8)*ldc + cc;
            if (EPI == 0) {
                *(float2*)(C + o0) = float2{ acc[ma][na][0], acc[ma][na][1] };
                *(float2*)(C + o1) = float2{ acc[ma][na][2], acc[ma][na][3] };
            } else if (EPI == 5) {
                *(__nv_bfloat162*)(Ch + o0) = __nv_bfloat162{
                    __float2bfloat16_rn(acc[ma][na][0]*scale), __float2bfloat16_rn(acc[ma][na][1]*scale) };
                *(__nv_bfloat162*)(Ch + o1) = __nv_bfloat162{
                    __float2bfloat16_rn(acc[ma][na][2]*scale), __float2bfloat16_rn(acc[ma][na][3]*scale) };
            } else if (EPI == 4) {
                *(__nv_bfloat162*)(Ch + o0) = __nv_bfloat162{
                    __float2bfloat16_rn(fmaxf(acc[ma][na][0],0.f)), __float2bfloat16_rn(fmaxf(acc[ma][na][1],0.f)) };
                *(__nv_bfloat162*)(Ch + o1) = __nv_bfloat162{
                    __float2bfloat16_rn(fmaxf(acc[ma][na][2],0.f)), __float2bfloat16_rn(fmaxf(acc[ma][na][3],0.f)) };
            } else {
                float v0 = acc[ma][na][0], v1 = acc[ma][na][1];
                float v2 = acc[ma][na][2], v3 = acc[ma][na][3];
                if (EPI == 3) { v0 = fmaxf(v0,0.f); v1 = fmaxf(v1,0.f);
                                v2 = fmaxf(v2,0.f); v3 = fmaxf(v3,0.f); }
                __nv_bfloat16 h0,l0,h1,l1,h2,l2,h3,l3;
                split_val(v0,h0,l0); split_val(v1,h1,l1);
                split_val(v2,h2,l2); split_val(v3,h3,l3);
                *(__nv_bfloat162*)(Ch + o0) = __nv_bfloat162{h0, h1};
                *(__nv_bfloat162*)(Cl + o0) = __nv_bfloat162{l0, l1};
                *(__nv_bfloat162*)(Ch + o1) = __nv_bfloat162{h2, h3};
                *(__nv_bfloat162*)(Cl + o1) = __nv_bfloat162{l2, l3};
            }
        }
    }
}

// ---------------- driver ----------------
extern "C" void kernel_launch(void* const* d_in, const int* in_sizes, int n_in,
                              void* d_out, int out_size) {
    const float* x_in  = (const float*)d_in[0];
    const float* gamma = (const float*)d_in[1];
    const float* delta = (const float*)d_in[2];
    const float* Wq    = (const float*)d_in[3];
    const float* Wk    = (const float*)d_in[4];
    const float* beta  = (const float*)d_in[5];
    const float* xi    = (const float*)d_in[6];
    float* x = (float*)d_out;

    __nv_bfloat16* bh = nullptr; float* fp = nullptr;
    cudaGetSymbolAddress((void**)&bh, g_bh);
    cudaGetSymbolAddress((void**)&fp, g_fp);

    __nv_bfloat16 *GH = bh+O_GH, *GL = bh+O_GL, *QKH = bh+O_QKH, *QKL = bh+O_QKL;
    __nv_bfloat16 *PH = bh+O_PH, *ABH = bh+O_AB, *AQH = bh+O_AQH, *AQL = bh+O_AQL;
    __nv_bfloat16 *HH = bh+O_HH, *WH = bh+O_WH, *WL = bh+O_WL;
    __nv_bfloat16 *WTH = bh+O_WTH, *WTL = bh+O_WTL, *XH = bh+O_XH, *XL = bh+O_XL;
    __nv_bfloat16 *XTH = bh+O_XTH, *XTL = bh+O_XTL;
    float *Gattn = fp+F_GA, *Ghop = fp+F_GO;
    float *meanb = fp+F_MEAN, *rstd = fp+F_RSTD;

    // smem bytes: STG halfs * 2B * 2 stages
    constexpr int SM_BIG  = (2*128*40 + 2*128*40) * 2 * 2;   // 81920 (NPROD3, 128/0/0)
    constexpr int SM_GHOP = (1*128*40 + 2*128*40) * 2 * 2;   // 61440 (NPROD2, 128/0/0)
    constexpr int SM_AQ   = (1*128*40 + 2*32*72) * 2 * 2;    // 38912 (64, A0 B2, NPROD2)
    constexpr int SM_AK   = (1*32*136 + 2*32*72) * 2 * 2;    // 35840 (64, A2 B2, NPROD2)
    cudaFuncSetAttribute(mma_gemm<128,0,0,3,0>, cudaFuncAttributeMaxDynamicSharedMemorySize, SM_BIG);
    cudaFuncSetAttribute(mma_gemm<128,0,0,3,2>, cudaFuncAttributeMaxDynamicSharedMemorySize, SM_BIG);
    cudaFuncSetAttribute(mma_gemm<128,0,0,3,4>, cudaFuncAttributeMaxDynamicSharedMemorySize, SM_BIG);
    cudaFuncSetAttribute(mma_gemm<128,0,0,3,5>, cudaFuncAttributeMaxDynamicSharedMemorySize, SM_BIG);
    cudaFuncSetAttribute(mma_gemm<128,0,0,2,0>, cudaFuncAttributeMaxDynamicSharedMemorySize, SM_GHOP);
    cudaFuncSetAttribute(mma_gemm<64,0,2,2,2>,  cudaFuncAttributeMaxDynamicSharedMemorySize, SM_AQ);
    cudaFuncSetAttribute(mma_gemm<64,2,2,2,2>,  cudaFuncAttributeMaxDynamicSharedMemorySize, SM_AK);

    // ---- setup (constant across steps) ----
    cudaMemcpyAsync(x, x_in, sizeof(float) * NG, cudaMemcpyDeviceToDevice);
    split_mat<<<2304, 256>>>(Wq, WH, WL);
    split_mat<<<2304, 256>>>(Wk, WH + 768*768, WL + 768*768);
    split_mat<<<9216, 256>>>(xi, XH, XL);
    transpose_split<<<dim3(24,24), dim3(32,8)>>>(Wq, 768, 768, WTH, WTL, 1536, 0);
    transpose_split<<<dim3(24,24), dim3(32,8)>>>(Wk, 768, 768, WTH, WTL, 1536, 768);
    transpose_split<<<dim3(24,96), dim3(32,8)>>>(xi, 3072, 768, XTH, XTL, 3072, 0);

    const long sQb = 1024L * 1536;
    const long sPz = (long)SS * SS;

    for (int step = 0; step < NSTEPS; step++) {
        // 1. LN forward -> g planes
        ln_forward<<<ROWS, 256>>>(x, gamma, delta, GH, GL, rstd, meanb);

        // 2. QK = g @ Wqk^T  (8192x1536, K=768)
        mma_gemm<128,0,0,3,2><<<dim3(12,64,1), 128, SM_BIG>>>(
            GH, GL, 768, 0, 0, WH, WL, 768, 0, 0,
            nullptr, QKH, QKL, 1536, 0, 0, 768, nullptr);

        // 3. scores = beta_h * Q K^T -> bf16  (96 x 1024x1024, K=64)
        mma_gemm<128,0,0,3,5><<<dim3(8,8,ZB), 128, SM_BIG>>>(
            QKH, QKL, 1536, sQb, 64,
            QKH + 768, QKL + 768, 1536, sQb, 64,
            nullptr, ABH, nullptr, SS, (long)N_HEADS * sPz, sPz, 64, beta);

        // 4. fused softmax (bf16 in) -> single P plane
        softmax_split<<<ZB * SS, 256>>>(ABH, PH);

        // 5. Aq = P @ K  (per z: 1024x64, K=1024)
        mma_gemm<64,0,2,2,2><<<dim3(1,8,ZB), 128, SM_AQ>>>(
            PH, nullptr, SS, (long)N_HEADS * sPz, sPz,
            QKH + 768, QKL + 768, 1536, sQb, 64,
            nullptr, AQH, AQL, 1536, sQb, 64, SS, nullptr);

        // 6. Ak = P^T @ Q
        mma_gemm<64,2,2,2,2><<<dim3(1,8,ZB), 128, SM_AK>>>(
            PH, nullptr, SS, (long)N_HEADS * sPz, sPz,
            QKH, QKL, 1536, sQb, 64,
            nullptr, AQH + 768, AQL + 768, 1536, sQb, 64, SS, nullptr);

        // 7. Gattn = AqAk @ Wqk  (8192x768, K=1536)
        mma_gemm<128,0,0,3,0><<<dim3(6,64,1), 128, SM_BIG>>>(
            AQH, AQL, 1536, 0, 0, WTH, WTL, 1536, 0, 0,
            Gattn, nullptr, nullptr, 768, 0, 0, 1536, nullptr);

        // 8. H = relu(g @ xi^T)  (8192x3072, K=768) -> single plane
        mma_gemm<128,0,0,3,4><<<dim3(24,64,1), 128, SM_BIG>>>(
            GH, GL, 768, 0, 0, XH, XL, 768, 0, 0,
            nullptr, HH, nullptr, 3072, 0, 0, 768, nullptr);

        // 9. Ghop = relu(H) @ xi  (8192x768, K=3072)
        mma_gemm<128,0,0,2,0><<<dim3(6,64,1), 128, SM_GHOP>>>(
            HH, nullptr, 3072, 0, 0, XTH, XTL, 3072, 0, 0,
            Ghop, nullptr, nullptr, 768, 0, 0, 3072, nullptr);

        // 10. LN backward + SGD update
        update_kernel<<<ROWS, 256>>>(x, Gattn, Ghop, gamma, meanb, rstd);
    }
}

// round 12
// speedup vs baseline: 5.2019x; 1.1868x over previous
#include <cuda_runtime.h>
#include <cuda_bf16.h>
#include <math.h>
#include <stdint.h>

// ---------------- problem constants ----------------
#define D_MODEL 768
#define N_HEADS 12
#define D_HEAD  64
#define N_MEM   3072
#define BB      8
#define SS      1024
#define ROWS    (BB*SS)        // 8192
#define ZB      (BB*N_HEADS)   // 96
#define ALPHA_F 0.1f
#define EPS_F   1e-5f
#define NSTEPS  12

// ---------------- element counts ----------------
constexpr long NG  = (long)ROWS * D_MODEL;
constexpr long NQK = (long)ROWS * 1536;
constexpr long NP  = (long)ZB * SS * SS;
constexpr long NH  = (long)ROWS * N_MEM;
constexpr long NW  = 1536L * 768;
constexpr long NXI = 3072L * 768;

// bf16 plane pool offsets (QK now hi-only; P, H single-plane)
constexpr long O_GH  = 0;            constexpr long O_GL  = O_GH  + NG;
constexpr long O_QKH = O_GL  + NG;
constexpr long O_PH  = O_QKH + NQK;
constexpr long O_AB  = O_PH  + NP;                       // bf16 scores (beta*A)
constexpr long O_AQH = O_AB  + NP;   constexpr long O_AQL = O_AQH + NQK;
constexpr long O_HH  = O_AQL + NQK;
constexpr long O_WH  = O_HH  + NH;   constexpr long O_WL  = O_WH  + NW;
constexpr long O_WTH = O_WL  + NW;   constexpr long O_WTL = O_WTH + NW;
constexpr long O_XH  = O_WTL + NW;   constexpr long O_XL  = O_XH  + NXI;
constexpr long O_XTH = O_XL  + NXI;  constexpr long O_XTL = O_XTH + NXI;
constexpr long TOT_B = O_XTL + NXI;

// fp32 pool offsets
constexpr long F_GA   = 0;
constexpr long F_GO   = F_GA + NG;
constexpr long F_MEAN = F_GO + NG;
constexpr long F_RSTD = F_MEAN + ROWS;
constexpr long TOT_F  = F_RSTD + ROWS;

__device__ __align__(256) __nv_bfloat16 g_bh[TOT_B];
__device__ __align__(256) float g_fp[TOT_F];

// ---------------- PTX helpers ----------------
__device__ __forceinline__ uint32_t smem_u32(const void* p) {
    uint32_t a;
    asm("{ .reg .u64 t; cvta.to.shared.u64 t, %1; cvt.u32.u64 %0, t; }" : "=r"(a) : "l"(p));
    return a;
}
__device__ __forceinline__ void cp16(uint32_t dst, const void* src) {
    asm volatile("cp.async.cg.shared.global [%0], [%1], 16;" :: "r"(dst), "l"(src));
}
__device__ __forceinline__ void cp_commit() {
    asm volatile("cp.async.commit_group;" ::: "memory");
}
template<int N> __device__ __forceinline__ void cp_wait() {
    asm volatile("cp.async.wait_group %0;" :: "n"(N) : "memory");
}
__device__ __forceinline__ void ldsm4(uint32_t* r, uint32_t a) {
    asm volatile("ldmatrix.sync.aligned.m8n8.x4.shared.b16 {%0,%1,%2,%3}, [%4];"
        : "=r"(r[0]), "=r"(r[1]), "=r"(r[2]), "=r"(r[3]) : "r"(a));
}
__device__ __forceinline__ void ldsm4t(uint32_t* r, uint32_t a) {
    asm volatile("ldmatrix.sync.aligned.m8n8.x4.trans.shared.b16 {%0,%1,%2,%3}, [%4];"
        : "=r"(r[0]), "=r"(r[1]), "=r"(r[2]), "=r"(r[3]) : "r"(a));
}
#define MMA16816(c, a, b) \
    asm volatile("mma.sync.aligned.m16n8k16.row.col.f32.bf16.bf16.f32 " \
        "{%0,%1,%2,%3}, {%4,%5,%6,%7}, {%8,%9}, {%0,%1,%2,%3};" \
        : "+f"(c[0]), "+f"(c[1]), "+f"(c[2]), "+f"(c[3]) \
        : "r"(a[0]), "r"(a[1]), "r"(a[2]), "r"(a[3]), "r"(b[0]), "r"(b[1]))

__device__ __forceinline__ void split_val(float v, __nv_bfloat16& h, __nv_bfloat16& l) {
    h = __float2bfloat16_rn(v);
    l = __float2bfloat16_rn(v - __bfloat162float(h));
}

// ---------------- reductions ----------------
__device__ __forceinline__ float warpSum(float v) {
    #pragma unroll
    for (int o = 16; o > 0; o >>= 1) v += __shfl_xor_sync(0xffffffffu, v, o);
    return v;
}
__device__ __forceinline__ float warpMax(float v) {
    #pragma unroll
    for (int o = 16; o > 0; o >>= 1) v = fmaxf(v, __shfl_xor_sync(0xffffffffu, v, o));
    return v;
}
__device__ __forceinline__ float blkSum(float v) {
    __shared__ float sh[32];
    int lane = threadIdx.x & 31, wid = threadIdx.x >> 5;
    __syncthreads();
    v = warpSum(v);
    if (lane == 0) sh[wid] = v;
    __syncthreads();
    int nw = (blockDim.x + 31) >> 5;
    v = (threadIdx.x < nw) ? sh[threadIdx.x] : 0.f;
    if (wid == 0) v = warpSum(v);
    return v;
}
__device__ __forceinline__ float blkMax(float v) {
    __shared__ float sh[32];
    int lane = threadIdx.x & 31, wid = threadIdx.x >> 5;
    __syncthreads();
    v = warpMax(v);
    if (lane == 0) sh[wid] = v;
    __syncthreads();
    int nw = (blockDim.x + 31) >> 5;
    v = (threadIdx.x < nw) ? sh[threadIdx.x] : -3.4e38f;
    if (wid == 0) v = warpMax(v);
    return v;
}

// ---------------- prep kernels ----------------
__global__ void split_mat(const float* __restrict__ src,
                          __nv_bfloat16* __restrict__ h, __nv_bfloat16* __restrict__ l) {
    long i = (long)blockIdx.x * 256 + threadIdx.x;
    __nv_bfloat16 a, b; split_val(src[i], a, b);
    h[i] = a; l[i] = b;
}
__global__ void transpose_split(const float* __restrict__ src, int R, int C,
                                __nv_bfloat16* __restrict__ dh, __nv_bfloat16* __restrict__ dl,
                                int ldD, int colOfs) {
    __shared__ float t[32][33];
    int c0 = blockIdx.x * 32, r0 = blockIdx.y * 32;
    int tx = threadIdx.x, ty = threadIdx.y;
    #pragma unroll
    for (int i = ty; i < 32; i += 8)
        t[i][tx] = src[(long)(r0 + i) * C + c0 + tx];
    __syncthreads();
    #pragma unroll
    for (int i = ty; i < 32; i += 8) {
        __nv_bfloat16 a, b; split_val(t[tx][i], a, b);
        long o = (long)(c0 + i) * ldD + colOfs + r0 + tx;
        dh[o] = a; dl[o] = b;
    }
}

// ---------------- LN forward (initial step only) ----------------
__global__ void ln_forward(const float* __restrict__ x,
                           const float* __restrict__ gamma,
                           const float* __restrict__ delta,
                           __nv_bfloat16* __restrict__ gh, __nv_bfloat16* __restrict__ gl,
                           float* __restrict__ rstd_o, float* __restrict__ mean_o) {
    int row = blockIdx.x;
    const float* xr = x + (long)row * D_MODEL;
    int t = threadIdx.x;
    float v[3]; float s = 0.f;
    #pragma unroll
    for (int i = 0; i < 3; i++) { v[i] = xr[t + i*256]; s += v[i]; }
    s = blkSum(s);
    __shared__ float shm, shr;
    if (t == 0) shm = s * (1.0f / D_MODEL);
    __syncthreads();
    float mean = shm;
    float q = 0.f;
    #pragma unroll
    for (int i = 0; i < 3; i++) { float d = v[i] - mean; q += d*d; }
    q = blkSum(q);
    if (t == 0) shr = rsqrtf(q * (1.0f / D_MODEL) + EPS_F);
    __syncthreads();
    float rstd = shr;
    float gm = gamma[0];
    long base = (long)row * D_MODEL;
    #pragma unroll
    for (int i = 0; i < 3; i++) {
        float g = gm * (v[i] - mean) * rstd + delta[t + i*256];
        __nv_bfloat16 a, b; split_val(g, a, b);
        gh[base + t + i*256] = a;
        gl[base + t + i*256] = b;
    }
    if (t == 0) { rstd_o[row] = rstd; mean_o[row] = mean; }
}

// ---------------- fused softmax over bf16 scores -> single bf16 P ----------------
__global__ void softmax_split(const __nv_bfloat16* __restrict__ A,
                              __nv_bfloat16* __restrict__ ph) {
    long row = blockIdx.x;
    const __nv_bfloat162* ar = (const __nv_bfloat162*)(A + row * SS);
    int t = threadIdx.x;
    __nv_bfloat162 b0 = ar[t*2], b1 = ar[t*2+1];
    float v0 = __bfloat162float(b0.x), v1 = __bfloat162float(b0.y);
    float v2 = __bfloat162float(b1.x), v3 = __bfloat162float(b1.y);
    float m = fmaxf(fmaxf(v0, v1), fmaxf(v2, v3));
    m = blkMax(m);
    __shared__ float shm, shi;
    if (t == 0) shm = m;
    __syncthreads();
    m = shm;
    float e0 = __expf(v0 - m), e1 = __expf(v1 - m);
    float e2 = __expf(v2 - m), e3 = __expf(v3 - m);
    float s = (e0 + e1) + (e2 + e3);
    s = blkSum(s);
    if (t == 0) shi = 1.0f / s;
    __syncthreads();
    float inv = shi;
    __nv_bfloat162* po = (__nv_bfloat162*)(ph + row * SS + t * 4);
    po[0] = __nv_bfloat162{ __float2bfloat16_rn(e0*inv), __float2bfloat16_rn(e1*inv) };
    po[1] = __nv_bfloat162{ __float2bfloat16_rn(e2*inv), __float2bfloat16_rn(e3*inv) };
}

// ---------------- fused LN-backward + SGD update (+ next-step LN forward) ----------------
template<bool DO_LN>
__global__ void update_ln(float* __restrict__ x,
                          const float* __restrict__ ga,
                          const float* __restrict__ ghp,
                          const float* __restrict__ gamma,
                          const float* __restrict__ delta,
                          const float* __restrict__ mean_a,
                          const float* __restrict__ rstd_a,
                          __nv_bfloat16* __restrict__ gh_o, __nv_bfloat16* __restrict__ gl_o,
                          float* __restrict__ rstd_o, float* __restrict__ mean_o) {
    int row = blockIdx.x;
    long base = (long)row * D_MODEL;
    int t = threadIdx.x;
    float mean = mean_a[row], rstd = rstd_a[row];
    float xv[3], uv[3], gv[3];
    float s1 = 0.f, s2 = 0.f;
    #pragma unroll
    for (int i = 0; i < 3; i++) {
        long idx = base + t + i*256;
        xv[i] = x[idx];
        uv[i] = xv[i] - ga[idx] - ghp[idx];
        gv[i] = (xv[i] - mean) * rstd;
        s1 += uv[i]; s2 += uv[i] * gv[i];
    }
    s1 = blkSum(s1);
    __shared__ float sh1, sh2;
    if (t == 0) sh1 = s1;
    s2 = blkSum(s2);
    if (t == 0) sh2 = s2;
    __syncthreads();
    float mu = sh1 * (1.0f / D_MODEL);
    float mg = sh2 * (1.0f / D_MODEL);
    float gm = gamma[0];
    float xn[3]; float ns = 0.f;
    #pragma unroll
    for (int i = 0; i < 3; i++) {
        float grad = gm * rstd * (uv[i] - mu - gv[i] * mg);
        xn[i] = xv[i] - ALPHA_F * grad;
        x[base + t + i*256] = xn[i];
        ns += xn[i];
    }
    if (!DO_LN) return;
    // ---- LN forward on the updated row ----
    ns = blkSum(ns);
    __shared__ float shm2, shr2;
    if (t == 0) shm2 = ns * (1.0f / D_MODEL);
    __syncthreads();
    float mean2 = shm2;
    float q = 0.f;
    #pragma unroll
    for (int i = 0; i < 3; i++) { float d = xn[i] - mean2; q += d*d; }
    q = blkSum(q);
    if (t == 0) shr2 = rsqrtf(q * (1.0f / D_MODEL) + EPS_F);
    __syncthreads();
    float rstd2 = shr2;
    #pragma unroll
    for (int i = 0; i < 3; i++) {
        float g = gm * (xn[i] - mean2) * rstd2 + delta[t + i*256];
        __nv_bfloat16 a, b; split_val(g, a, b);
        gh_o[base + t + i*256] = a;
        gl_o[base + t + i*256] = b;
    }
    if (t == 0) { rstd_o[row] = rstd2; mean_o[row] = mean2; }
}

// ---------------- mma.sync bf16 split-emulated GEMM ----------------
// 128 threads, 4 warps, warp tile 64 x (BN/2). 2-stage cp.async, single sync/chunk.
// NPROD: 3 -> AhBh + AhBl + AlBh ; 2 -> AhBh + AhBl (A hi only) ; 1 -> AhBh (both hi)
// AMODE/BMODE: 0 -> gmem [row][k] K-major; 2 -> gmem [k][row] (ldmatrix.trans)
// EPI: 0 fp32 | 2 split hi+lo | 3 relu+split | 4 relu+hi | 5 beta-scaled bf16 | 6 plain bf16 hi
template<int BN, int AMODE, int BMODE, int NPROD, int EPI>
__global__ void __launch_bounds__(128)
mma_gemm(const __nv_bfloat16* __restrict__ Ah, const __nv_bfloat16* __restrict__ Al,
         int lda, long sAb, long sAh,
         const __nv_bfloat16* __restrict__ Bh, const __nv_bfloat16* __restrict__ Bl,
         int ldb, long sBb, long sBh,
         float* __restrict__ C,
         __nv_bfloat16* __restrict__ Ch, __nv_bfloat16* __restrict__ Cl,
         int ldc, long sCb, long sCh,
         int K, const float* __restrict__ betaP) {
    constexpr int BM = 128, BK = 32;
    constexpr int WTN = BN / 2;
    constexpr int MA = 4;
    constexpr int NA = WTN / 8;
    constexpr int SAn = 40;
    constexpr int SAtA = BM + 8;
    constexpr int SAtB = BN + 8;
    constexpr int szA = (AMODE == 0) ? BM * SAn : BK * SAtA;
    constexpr int szB = (BMODE == 0) ? BN * SAn : BK * SAtB;
    constexpr int NAP = (NPROD == 3) ? 2 : 1;
    constexpr int NBP = (NPROD >= 2) ? 2 : 1;
    constexpr int OFF_BH_ = NAP * szA;
    constexpr int OFF_BL_ = OFF_BH_ + szB;
    constexpr int STG = NAP * szA + NBP * szB;

    extern __shared__ __nv_bfloat16 smh[];

    int tid = threadIdx.x;
    int wid = tid >> 5, lane = tid & 31;
    int wm = wid & 1, wn = wid >> 1;

    int zb = blockIdx.z / N_HEADS, zh = blockIdx.z % N_HEADS;
    const __nv_bfloat16* pAh = Ah + (long)zb * sAb + (long)zh * sAh;
    const __nv_bfloat16* pAl = (NPROD == 3) ? Al + (long)zb * sAb + (long)zh * sAh : nullptr;
    const __nv_bfloat16* pBh = Bh + (long)zb * sBb + (long)zh * sBh;
    const __nv_bfloat16* pBl = (NPROD >= 2) ? Bl + (long)zb * sBb + (long)zh * sBh : nullptr;
    long cOff = (long)zb * sCb + (long)zh * sCh;
    int bm = blockIdx.y * BM, bn = blockIdx.x * BN;

    float acc[MA][NA][4];
    #pragma unroll
    for (int i = 0; i < MA; i++)
        #pragma unroll
        for (int j = 0; j < NA; j++)
            #pragma unroll
            for (int e = 0; e < 4; e++) acc[i][j][e] = 0.f;

    auto loadA = [&](__nv_bfloat16* sd, const __nv_bfloat16* gp, int k0) {
        if (AMODE == 0) {
            #pragma unroll
            for (int j = 0; j < BM * 4; j += 128) {
                int id = tid + j, r = id >> 2, sg = id & 3;
                cp16(smem_u32(sd + r * SAn + sg * 8), gp + (long)(bm + r) * lda + k0 + sg * 8);
            }
        } else {
            constexpr int CPR = BM / 8;
            #pragma unroll
            for (int j = 0; j < BK * CPR; j += 128) {
                int id = tid + j, kk = id / CPR, sg = id % CPR;
                cp16(smem_u32(sd + kk * SAtA + sg * 8), gp + (long)(k0 + kk) * lda + bm + sg * 8);
            }
        }
    };
    auto loadB = [&](__nv_bfloat16* sd, const __nv_bfloat16* gp, int k0) {
        if (BMODE == 0) {
            #pragma unroll
            for (int j = 0; j < BN * 4; j += 128) {
                int id = tid + j, r = id >> 2, sg = id & 3;
                cp16(smem_u32(sd + r * SAn + sg * 8), gp + (long)(bn + r) * ldb + k0 + sg * 8);
            }
        } else {
            constexpr int CPR = BN / 8;
            #pragma unroll
            for (int j = 0; j < BK * CPR; j += 128) {
                int id = tid + j, kk = id / CPR, sg = id % CPR;
                cp16(smem_u32(sd + kk * SAtB + sg * 8), gp + (long)(k0 + kk) * ldb + bn + sg * 8);
            }
        }
    };
    auto prefetch = [&](__nv_bfloat16* st, int k0) {
        loadA(st, pAh, k0);
        if (NPROD == 3) loadA(st + szA, pAl, k0);
        loadB(st + OFF_BH_, pBh, k0);
        if (NPROD >= 2) loadB(st + OFF_BL_, pBl, k0);
        cp_commit();
    };

    auto compute = [&](const __nv_bfloat16* cur) {
        const __nv_bfloat16* As_ = cur;
        const __nv_bfloat16* Al_ = cur + szA;
        const __nv_bfloat16* Bs_ = cur + OFF_BH_;
        const __nv_bfloat16* Bl_ = cur + OFF_BL_;
        #pragma unroll
        for (int ks = 0; ks < 2; ks++) {
            int ko = ks * 16;
            uint32_t bhf[NA][2], blf[NA][2];
            #pragma unroll
            for (int pr = 0; pr < NA/2; pr++) {
                uint32_t r[4], rl[4];
                if (BMODE == 0) {
                    int q = lane >> 3, idx = lane & 7;
                    int nrow = wn * WTN + pr * 16 + (q >> 1) * 8 + idx;
                    int kcol = ko + (q & 1) * 8;
                    ldsm4(r, smem_u32(Bs_ + nrow * SAn + kcol));
                    if (NPROD >= 2) ldsm4(rl, smem_u32(Bl_ + nrow * SAn + kcol));
                } else {
                    int krow = ko + ((lane >> 3) & 1) * 8 + (lane & 7);
                    int ncol = wn * WTN + pr * 16 + (lane >> 4) * 8;
                    ldsm4t(r, smem_u32(Bs_ + krow * SAtB + ncol));
                    if (NPROD >= 2) ldsm4t(rl, smem_u32(Bl_ + krow * SAtB + ncol));
                }
                bhf[pr*2][0] = r[0];  bhf[pr*2][1] = r[1];
                bhf[pr*2+1][0] = r[2]; bhf[pr*2+1][1] = r[3];
                if (NPROD >= 2) {
                    blf[pr*2][0] = rl[0]; blf[pr*2][1] = rl[1];
                    blf[pr*2+1][0] = rl[2]; blf[pr*2+1][1] = rl[3];
                }
            }
            #pragma unroll
            for (int ma = 0; ma < MA; ma++) {
                uint32_t ahf[4], alf[4];
                if (AMODE == 0) {
                    int arow = wm * 64 + ma * 16 + (lane & 15);
                    int akcol = ko + (lane >> 4) * 8;
                    ldsm4(ahf, smem_u32(As_ + arow * SAn + akcol));
                    if (NPROD == 3) ldsm4(alf, smem_u32(Al_ + arow * SAn + akcol));
                } else {
                    int akrow = ko + (lane & 7) + (lane >> 4) * 8;
                    int amcol = wm * 64 + ma * 16 + ((lane >> 3) & 1) * 8;
                    ldsm4t(ahf, smem_u32(As_ + akrow * SAtA + amcol));
                    if (NPROD == 3) ldsm4t(alf, smem_u32(Al_ + akrow * SAtA + amcol));
                }
                #pragma unroll
                for (int na = 0; na < NA; na++) {
                    MMA16816(acc[ma][na], ahf, bhf[na]);
                    if (NPROD >= 2) MMA16816(acc[ma][na], ahf, blf[na]);
                    if (NPROD == 3) MMA16816(acc[ma][na], alf, bhf[na]);
                }
            }
        }
    };

    int nCh = K >> 5;
    prefetch(smh, 0);
    for (int c = 0; c < nCh; c++) {
        cp_wait<0>();
        __syncthreads();
        if (c + 1 < nCh) prefetch(smh + ((c + 1) & 1) * STG, (c + 1) << 5);
        compute(smh + (c & 1) * STG);
    }

    // ---- epilogue ----
    int g = lane >> 2, tig = lane & 3;
    float scale = (EPI == 5) ? betaP[zh] : 1.0f;
    #pragma unroll
    for (int ma = 0; ma < MA; ma++) {
        #pragma unroll
        for (int na = 0; na < NA; na++) {
            int r = bm + wm*64 + ma*16 + g;
            int cc = bn + wn*WTN + na*8 + tig*2;
            long o0 = cOff + (long)r*ldc + cc;
            long o1 = cOff + (long)(r+8)*ldc + cc;
            if (EPI == 0) {
                *(float2*)(C + o0) = float2{ acc[ma][na][0], acc[ma][na][1] };
                *(float2*)(C + o1) = float2{ acc[ma][na][2], acc[ma][na][3] };
            } else if (EPI == 5) {
                *(__nv_bfloat162*)(Ch + o0) = __nv_bfloat162{
                    __float2bfloat16_rn(acc[ma][na][0]*scale), __float2bfloat16_rn(acc[ma][na][1]*scale) };
                *(__nv_bfloat162*)(Ch + o1) = __nv_bfloat162{
                    __float2bfloat16_rn(acc[ma][na][2]*scale), __float2bfloat16_rn(acc[ma][na][3]*scale) };
            } else if (EPI == 6) {
                *(__nv_bfloat162*)(Ch + o0) = __nv_bfloat162{
                    __float2bfloat16_rn(acc[ma][na][0]), __float2bfloat16_rn(acc[ma][na][1]) };
                *(__nv_bfloat162*)(Ch + o1) = __nv_bfloat162{
                    __float2bfloat16_rn(acc[ma][na][2]), __float2bfloat16_rn(acc[ma][na][3]) };
            } else if (EPI == 4) {
                *(__nv_bfloat162*)(Ch + o0) = __nv_bfloat162{
                    __float2bfloat16_rn(fmaxf(acc[ma][na][0],0.f)), __float2bfloat16_rn(fmaxf(acc[ma][na][1],0.f)) };
                *(__nv_bfloat162*)(Ch + o1) = __nv_bfloat162{
                    __float2bfloat16_rn(fmaxf(acc[ma][na][2],0.f)), __float2bfloat16_rn(fmaxf(acc[ma][na][3],0.f)) };
            } else {
                float v0 = acc[ma][na][0], v1 = acc[ma][na][1];
                float v2 = acc[ma][na][2], v3 = acc[ma][na][3];
                if (EPI == 3) { v0 = fmaxf(v0,0.f); v1 = fmaxf(v1,0.f);
                                v2 = fmaxf(v2,0.f); v3 = fmaxf(v3,0.f); }
                __nv_bfloat16 h0,l0,h1,l1,h2,l2,h3,l3;
                split_val(v0,h0,l0); split_val(v1,h1,l1);
                split_val(v2,h2,l2); split_val(v3,h3,l3);
                *(__nv_bfloat162*)(Ch + o0) = __nv_bfloat162{h0, h1};
                *(__nv_bfloat162*)(Cl + o0) = __nv_bfloat162{l0, l1};
                *(__nv_bfloat162*)(Ch + o1) = __nv_bfloat162{h2, h3};
                *(__nv_bfloat162*)(Cl + o1) = __nv_bfloat162{l2, l3};
            }
        }
    }
}

// ---------------- driver ----------------
extern "C" void kernel_launch(void* const* d_in, const int* in_sizes, int n_in,
                              void* d_out, int out_size) {
    const float* x_in  = (const float*)d_in[0];
    const float* gamma = (const float*)d_in[1];
    const float* delta = (const float*)d_in[2];
    const float* Wq    = (const float*)d_in[3];
    const float* Wk    = (const float*)d_in[4];
    const float* beta  = (const float*)d_in[5];
    const float* xi    = (const float*)d_in[6];
    float* x = (float*)d_out;

    __nv_bfloat16* bh = nullptr; float* fp = nullptr;
    cudaGetSymbolAddress((void**)&bh, g_bh);
    cudaGetSymbolAddress((void**)&fp, g_fp);

    __nv_bfloat16 *GH = bh+O_GH, *GL = bh+O_GL, *QKH = bh+O_QKH;
    __nv_bfloat16 *PH = bh+O_PH, *ABH = bh+O_AB, *AQH = bh+O_AQH, *AQL = bh+O_AQL;
    __nv_bfloat16 *HH = bh+O_HH, *WH = bh+O_WH, *WL = bh+O_WL;
    __nv_bfloat16 *WTH = bh+O_WTH, *WTL = bh+O_WTL, *XH = bh+O_XH, *XL = bh+O_XL;
    __nv_bfloat16 *XTH = bh+O_XTH, *XTL = bh+O_XTL;
    float *Gattn = fp+F_GA, *Ghop = fp+F_GO;
    float *meanb = fp+F_MEAN, *rstd = fp+F_RSTD;

    // smem bytes: STG halfs * 2B * 2 stages
    constexpr int SM_N3   = (2*128*40 + 2*128*40) * 2 * 2;   // 81920 (Gattn)
    constexpr int SM_N2   = (1*128*40 + 2*128*40) * 2 * 2;   // 61440 (QK, H, Ghop)
    constexpr int SM_N1   = (1*128*40 + 1*128*40) * 2 * 2;   // 40960 (scores)
    constexpr int SM_AQ   = (1*128*40 + 1*32*72) * 2 * 2;    // 29696
    constexpr int SM_AK   = (1*32*136 + 1*32*72) * 2 * 2;    // 26624
    cudaFuncSetAttribute(mma_gemm<128,0,0,3,0>, cudaFuncAttributeMaxDynamicSharedMemorySize, SM_N3);
    cudaFuncSetAttribute(mma_gemm<128,0,0,2,6>, cudaFuncAttributeMaxDynamicSharedMemorySize, SM_N2);
    cudaFuncSetAttribute(mma_gemm<128,0,0,2,4>, cudaFuncAttributeMaxDynamicSharedMemorySize, SM_N2);
    cudaFuncSetAttribute(mma_gemm<128,0,0,2,0>, cudaFuncAttributeMaxDynamicSharedMemorySize, SM_N2);
    cudaFuncSetAttribute(mma_gemm<128,0,0,1,5>, cudaFuncAttributeMaxDynamicSharedMemorySize, SM_N1);
    cudaFuncSetAttribute(mma_gemm<64,0,2,1,2>,  cudaFuncAttributeMaxDynamicSharedMemorySize, SM_AQ);
    cudaFuncSetAttribute(mma_gemm<64,2,2,1,2>,  cudaFuncAttributeMaxDynamicSharedMemorySize, SM_AK);

    // ---- setup (constant across steps) ----
    cudaMemcpyAsync(x, x_in, sizeof(float) * NG, cudaMemcpyDeviceToDevice);
    split_mat<<<2304, 256>>>(Wq, WH, WL);
    split_mat<<<2304, 256>>>(Wk, WH + 768*768, WL + 768*768);
    split_mat<<<9216, 256>>>(xi, XH, XL);
    transpose_split<<<dim3(24,24), dim3(32,8)>>>(Wq, 768, 768, WTH, WTL, 1536, 0);
    transpose_split<<<dim3(24,24), dim3(32,8)>>>(Wk, 768, 768, WTH, WTL, 1536, 768);
    transpose_split<<<dim3(24,96), dim3(32,8)>>>(xi, 3072, 768, XTH, XTL, 3072, 0);

    // initial LN
    ln_forward<<<ROWS, 256>>>(x, gamma, delta, GH, GL, rstd, meanb);

    const long sQb = 1024L * 1536;
    const long sPz = (long)SS * SS;

    for (int step = 0; step < NSTEPS; step++) {
        // 1. QK = g @ Wqk^T  (8192x1536, K=768), 2 products, hi-only out
        mma_gemm<128,0,0,2,6><<<dim3(12,64,1), 128, SM_N2>>>(
            GH, GL, 768, 0, 0, WH, WL, 768, 0, 0,
            nullptr, QKH, nullptr, 1536, 0, 0, 768, nullptr);

        // 2. scores = beta_h * Q K^T -> bf16  (pure bf16, 1 product)
        mma_gemm<128,0,0,1,5><<<dim3(8,8,ZB), 128, SM_N1>>>(
            QKH, nullptr, 1536, sQb, 64,
            QKH + 768, nullptr, 1536, sQb, 64,
            nullptr, ABH, nullptr, SS, (long)N_HEADS * sPz, sPz, 64, beta);

        // 3. fused softmax -> single P plane
        softmax_split<<<ZB * SS, 256>>>(ABH, PH);

        // 4. Aq = P @ K  (1 product)
        mma_gemm<64,0,2,1,2><<<dim3(1,8,ZB), 128, SM_AQ>>>(
            PH, nullptr, SS, (long)N_HEADS * sPz, sPz,
            QKH + 768, nullptr, 1536, sQb, 64,
            nullptr, AQH, AQL, 1536, sQb, 64, SS, nullptr);

        // 5. Ak = P^T @ Q  (1 product)
        mma_gemm<64,2,2,1,2><<<dim3(1,8,ZB), 128, SM_AK>>>(
            PH, nullptr, SS, (long)N_HEADS * sPz, sPz,
            QKH, nullptr, 1536, sQb, 64,
            nullptr, AQH + 768, AQL + 768, 1536, sQb, 64, SS, nullptr);

        // 6. Gattn = AqAk @ Wqk  (full 3-product, fp32 out)
        mma_gemm<128,0,0,3,0><<<dim3(6,64,1), 128, SM_N3>>>(
            AQH, AQL, 1536, 0, 0, WTH, WTL, 1536, 0, 0,
            Gattn, nullptr, nullptr, 768, 0, 0, 1536, nullptr);

        // 7. H = relu(g @ xi^T)  (2 products, hi-only out)
        mma_gemm<128,0,0,2,4><<<dim3(24,64,1), 128, SM_N2>>>(
            GH, GL, 768, 0, 0, XH, XL, 768, 0, 0,
            nullptr, HH, nullptr, 3072, 0, 0, 768, nullptr);

        // 8. Ghop = relu(H) @ xi  (2 products, fp32 out)
        mma_gemm<128,0,0,2,0><<<dim3(6,64,1), 128, SM_N2>>>(
            HH, nullptr, 3072, 0, 0, XTH, XTL, 3072, 0, 0,
            Ghop, nullptr, nullptr, 768, 0, 0, 3072, nullptr);

        // 9. LN backward + SGD update (+ fused next-step LN forward)
        if (step < NSTEPS - 1)
            update_ln<true><<<ROWS, 256>>>(x, Gattn, Ghop, gamma, delta,
                                           meanb, rstd, GH, GL, rstd, meanb);
        else
            update_ln<false><<<ROWS, 256>>>(x, Gattn, Ghop, gamma, delta,
                                            meanb, rstd, nullptr, nullptr, nullptr, nullptr);
    }
}

// round 16
// speedup vs baseline: 5.2153x; 1.0026x over previous
#include <cuda_runtime.h>
#include <cuda_bf16.h>
#include <math.h>
#include <stdint.h>

// ---------------- problem constants ----------------
#define D_MODEL 768
#define N_HEADS 12
#define D_HEAD  64
#define N_MEM   3072
#define BB      8
#define SS      1024
#define ROWS    (BB*SS)        // 8192
#define ZB      (BB*N_HEADS)   // 96
#define ALPHA_F 0.1f
#define EPS_F   1e-5f
#define NSTEPS  12

// ---------------- element counts ----------------
constexpr long NG  = (long)ROWS * D_MODEL;
constexpr long NQK = (long)ROWS * 1536;
constexpr long NP  = (long)ZB * SS * SS;
constexpr long NH  = (long)ROWS * N_MEM;
constexpr long NW  = 1536L * 768;
constexpr long NXI = 3072L * 768;

// bf16 plane pool offsets (QK hi-only; P, H single-plane)
constexpr long O_GH  = 0;            constexpr long O_GL  = O_GH  + NG;
constexpr long O_QKH = O_GL  + NG;
constexpr long O_PH  = O_QKH + NQK;
constexpr long O_AB  = O_PH  + NP;                       // bf16 scores (beta*A)
constexpr long O_AQH = O_AB  + NP;   constexpr long O_AQL = O_AQH + NQK;
constexpr long O_HH  = O_AQL + NQK;
constexpr long O_WH  = O_HH  + NH;   constexpr long O_WL  = O_WH  + NW;
constexpr long O_WTH = O_WL  + NW;   constexpr long O_WTL = O_WTH + NW;
constexpr long O_XH  = O_WTL + NW;   constexpr long O_XL  = O_XH  + NXI;
constexpr long O_XTH = O_XL  + NXI;  constexpr long O_XTL = O_XTH + NXI;
constexpr long TOT_B = O_XTL + NXI;

// fp32 pool offsets
constexpr long F_GA   = 0;
constexpr long F_GO   = F_GA + NG;
constexpr long F_MEAN = F_GO + NG;
constexpr long F_RSTD = F_MEAN + ROWS;
constexpr long TOT_F  = F_RSTD + ROWS;

__device__ __align__(256) __nv_bfloat16 g_bh[TOT_B];
__device__ __align__(256) float g_fp[TOT_F];

// ---------------- PTX helpers ----------------
__device__ __forceinline__ uint32_t smem_u32(const void* p) {
    uint32_t a;
    asm("{ .reg .u64 t; cvta.to.shared.u64 t, %1; cvt.u32.u64 %0, t; }" : "=r"(a) : "l"(p));
    return a;
}
__device__ __forceinline__ void cp16(uint32_t dst, const void* src) {
    asm volatile("cp.async.cg.shared.global [%0], [%1], 16;" :: "r"(dst), "l"(src));
}
__device__ __forceinline__ void cp_commit() {
    asm volatile("cp.async.commit_group;" ::: "memory");
}
template<int N> __device__ __forceinline__ void cp_wait() {
    asm volatile("cp.async.wait_group %0;" :: "n"(N) : "memory");
}
__device__ __forceinline__ void ldsm4(uint32_t* r, uint32_t a) {
    asm volatile("ldmatrix.sync.aligned.m8n8.x4.shared.b16 {%0,%1,%2,%3}, [%4];"
        : "=r"(r[0]), "=r"(r[1]), "=r"(r[2]), "=r"(r[3]) : "r"(a));
}
__device__ __forceinline__ void ldsm4t(uint32_t* r, uint32_t a) {
    asm volatile("ldmatrix.sync.aligned.m8n8.x4.trans.shared.b16 {%0,%1,%2,%3}, [%4];"
        : "=r"(r[0]), "=r"(r[1]), "=r"(r[2]), "=r"(r[3]) : "r"(a));
}
#define MMA16816(c, a, b) \
    asm volatile("mma.sync.aligned.m16n8k16.row.col.f32.bf16.bf16.f32 " \
        "{%0,%1,%2,%3}, {%4,%5,%6,%7}, {%8,%9}, {%0,%1,%2,%3};" \
        : "+f"(c[0]), "+f"(c[1]), "+f"(c[2]), "+f"(c[3]) \
        : "r"(a[0]), "r"(a[1]), "r"(a[2]), "r"(a[3]), "r"(b[0]), "r"(b[1]))

__device__ __forceinline__ void split_val(float v, __nv_bfloat16& h, __nv_bfloat16& l) {
    h = __float2bfloat16_rn(v);
    l = __float2bfloat16_rn(v - __bfloat162float(h));
}

// ---------------- reductions ----------------
__device__ __forceinline__ float warpSum(float v) {
    #pragma unroll
    for (int o = 16; o > 0; o >>= 1) v += __shfl_xor_sync(0xffffffffu, v, o);
    return v;
}
__device__ __forceinline__ float warpMax(float v) {
    #pragma unroll
    for (int o = 16; o > 0; o >>= 1) v = fmaxf(v, __shfl_xor_sync(0xffffffffu, v, o));
    return v;
}
__device__ __forceinline__ float blkSum(float v) {
    __shared__ float sh[32];
    int lane = threadIdx.x & 31, wid = threadIdx.x >> 5;
    __syncthreads();
    v = warpSum(v);
    if (lane == 0) sh[wid] = v;
    __syncthreads();
    int nw = (blockDim.x + 31) >> 5;
    v = (threadIdx.x < nw) ? sh[threadIdx.x] : 0.f;
    if (wid == 0) v = warpSum(v);
    return v;
}
__device__ __forceinline__ float blkMax(float v) {
    __shared__ float sh[32];
    int lane = threadIdx.x & 31, wid = threadIdx.x >> 5;
    __syncthreads();
    v = warpMax(v);
    if (lane == 0) sh[wid] = v;
    __syncthreads();
    int nw = (blockDim.x + 31) >> 5;
    v = (threadIdx.x < nw) ? sh[threadIdx.x] : -3.4e38f;
    if (wid == 0) v = warpMax(v);
    return v;
}

// ---------------- prep kernels ----------------
__global__ void split_mat(const float* __restrict__ src,
                          __nv_bfloat16* __restrict__ h, __nv_bfloat16* __restrict__ l) {
    long i = (long)blockIdx.x * 256 + threadIdx.x;
    __nv_bfloat16 a, b; split_val(src[i], a, b);
    h[i] = a; l[i] = b;
}
__global__ void transpose_split(const float* __restrict__ src, int R, int C,
                                __nv_bfloat16* __restrict__ dh, __nv_bfloat16* __restrict__ dl,
                                int ldD, int colOfs) {
    __shared__ float t[32][33];
    int c0 = blockIdx.x * 32, r0 = blockIdx.y * 32;
    int tx = threadIdx.x, ty = threadIdx.y;
    #pragma unroll
    for (int i = ty; i < 32; i += 8)
        t[i][tx] = src[(long)(r0 + i) * C + c0 + tx];
    __syncthreads();
    #pragma unroll
    for (int i = ty; i < 32; i += 8) {
        __nv_bfloat16 a, b; split_val(t[tx][i], a, b);
        long o = (long)(c0 + i) * ldD + colOfs + r0 + tx;
        dh[o] = a; dl[o] = b;
    }
}

// ---------------- LN forward (initial step only) ----------------
__global__ void ln_forward(const float* __restrict__ x,
                           const float* __restrict__ gamma,
                           const float* __restrict__ delta,
                           __nv_bfloat16* __restrict__ gh, __nv_bfloat16* __restrict__ gl,
                           float* __restrict__ rstd_o, float* __restrict__ mean_o) {
    int row = blockIdx.x;
    const float* xr = x + (long)row * D_MODEL;
    int t = threadIdx.x;
    float v[3]; float s = 0.f;
    #pragma unroll
    for (int i = 0; i < 3; i++) { v[i] = xr[t + i*256]; s += v[i]; }
    s = blkSum(s);
    __shared__ float shm, shr;
    if (t == 0) shm = s * (1.0f / D_MODEL);
    __syncthreads();
    float mean = shm;
    float q = 0.f;
    #pragma unroll
    for (int i = 0; i < 3; i++) { float d = v[i] - mean; q += d*d; }
    q = blkSum(q);
    if (t == 0) shr = rsqrtf(q * (1.0f / D_MODEL) + EPS_F);
    __syncthreads();
    float rstd = shr;
    float gm = gamma[0];
    long base = (long)row * D_MODEL;
    #pragma unroll
    for (int i = 0; i < 3; i++) {
        float g = gm * (v[i] - mean) * rstd + delta[t + i*256];
        __nv_bfloat16 a, b; split_val(g, a, b);
        gh[base + t + i*256] = a;
        gl[base + t + i*256] = b;
    }
    if (t == 0) { rstd_o[row] = rstd; mean_o[row] = mean; }
}

// ---------------- fused softmax over bf16 scores -> single bf16 P ----------------
__global__ void softmax_split(const __nv_bfloat16* __restrict__ A,
                              __nv_bfloat16* __restrict__ ph) {
    long row = blockIdx.x;
    const __nv_bfloat162* ar = (const __nv_bfloat162*)(A + row * SS);
    int t = threadIdx.x;
    __nv_bfloat162 b0 = ar[t*2], b1 = ar[t*2+1];
    float v0 = __bfloat162float(b0.x), v1 = __bfloat162float(b0.y);
    float v2 = __bfloat162float(b1.x), v3 = __bfloat162float(b1.y);
    float m = fmaxf(fmaxf(v0, v1), fmaxf(v2, v3));
    m = blkMax(m);
    __shared__ float shm, shi;
    if (t == 0) shm = m;
    __syncthreads();
    m = shm;
    float e0 = __expf(v0 - m), e1 = __expf(v1 - m);
    float e2 = __expf(v2 - m), e3 = __expf(v3 - m);
    float s = (e0 + e1) + (e2 + e3);
    s = blkSum(s);
    if (t == 0) shi = 1.0f / s;
    __syncthreads();
    float inv = shi;
    __nv_bfloat162* po = (__nv_bfloat162*)(ph + row * SS + t * 4);
    po[0] = __nv_bfloat162{ __float2bfloat16_rn(e0*inv), __float2bfloat16_rn(e1*inv) };
    po[1] = __nv_bfloat162{ __float2bfloat16_rn(e2*inv), __float2bfloat16_rn(e3*inv) };
}

// ---------------- fused LN-backward + SGD update (+ next-step LN forward) ----------------
template<bool DO_LN>
__global__ void update_ln(float* __restrict__ x,
                          const float* __restrict__ ga,
                          const float* __restrict__ ghp,
                          const float* __restrict__ gamma,
                          const float* __restrict__ delta,
                          const float* __restrict__ mean_a,
                          const float* __restrict__ rstd_a,
                          __nv_bfloat16* __restrict__ gh_o, __nv_bfloat16* __restrict__ gl_o,
                          float* __restrict__ rstd_o, float* __restrict__ mean_o) {
    int row = blockIdx.x;
    long base = (long)row * D_MODEL;
    int t = threadIdx.x;
    float mean = mean_a[row], rstd = rstd_a[row];
    float xv[3], uv[3], gv[3];
    float s1 = 0.f, s2 = 0.f;
    #pragma unroll
    for (int i = 0; i < 3; i++) {
        long idx = base + t + i*256;
        xv[i] = x[idx];
        uv[i] = xv[i] - ga[idx] - ghp[idx];
        gv[i] = (xv[i] - mean) * rstd;
        s1 += uv[i]; s2 += uv[i] * gv[i];
    }
    s1 = blkSum(s1);
    __shared__ float sh1, sh2;
    if (t == 0) sh1 = s1;
    s2 = blkSum(s2);
    if (t == 0) sh2 = s2;
    __syncthreads();
    float mu = sh1 * (1.0f / D_MODEL);
    float mg = sh2 * (1.0f / D_MODEL);
    float gm = gamma[0];
    float xn[3]; float ns = 0.f;
    #pragma unroll
    for (int i = 0; i < 3; i++) {
        float grad = gm * rstd * (uv[i] - mu - gv[i] * mg);
        xn[i] = xv[i] - ALPHA_F * grad;
        x[base + t + i*256] = xn[i];
        ns += xn[i];
    }
    if (!DO_LN) return;
    ns = blkSum(ns);
    __shared__ float shm2, shr2;
    if (t == 0) shm2 = ns * (1.0f / D_MODEL);
    __syncthreads();
    float mean2 = shm2;
    float q = 0.f;
    #pragma unroll
    for (int i = 0; i < 3; i++) { float d = xn[i] - mean2; q += d*d; }
    q = blkSum(q);
    if (t == 0) shr2 = rsqrtf(q * (1.0f / D_MODEL) + EPS_F);
    __syncthreads();
    float rstd2 = shr2;
    #pragma unroll
    for (int i = 0; i < 3; i++) {
        float g = gm * (xn[i] - mean2) * rstd2 + delta[t + i*256];
        __nv_bfloat16 a, b; split_val(g, a, b);
        gh_o[base + t + i*256] = a;
        gl_o[base + t + i*256] = b;
    }
    if (t == 0) { rstd_o[row] = rstd2; mean_o[row] = mean2; }
}

// ---------------- mma.sync bf16 split-emulated GEMM ----------------
// 128 threads, 4 warps, warp tile 64 x (BN/2). 2-stage cp.async, single sync/chunk.
// NPROD: 3 -> AhBh + AhBl + AlBh ; 2 -> AhBh + AhBl ; 1 -> AhBh
// Product-major MMA scheduling: all fragments loaded first, then per-product passes
// over independent accumulator tiles (dependency distance MA*NA instead of 1).
// AMODE/BMODE: 0 -> gmem [row][k] K-major; 2 -> gmem [k][row] (ldmatrix.trans)
// EPI: 0 fp32 | 2 split hi+lo | 3 relu+split | 4 relu+hi | 5 beta-scaled bf16 | 6 bf16 hi
template<int BN, int AMODE, int BMODE, int NPROD, int EPI>
__global__ void __launch_bounds__(128)
mma_gemm(const __nv_bfloat16* __restrict__ Ah, const __nv_bfloat16* __restrict__ Al,
         int lda, long sAb, long sAh,
         const __nv_bfloat16* __restrict__ Bh, const __nv_bfloat16* __restrict__ Bl,
         int ldb, long sBb, long sBh,
         float* __restrict__ C,
         __nv_bfloat16* __restrict__ Ch, __nv_bfloat16* __restrict__ Cl,
         int ldc, long sCb, long sCh,
         int K, const float* __restrict__ betaP) {
    constexpr int BM = 128, BK = 32;
    constexpr int WTN = BN / 2;
    constexpr int MA = 4;
    constexpr int NA = WTN / 8;
    constexpr int SAn = 40;
    constexpr int SAtA = BM + 8;
    constexpr int SAtB = BN + 8;
    constexpr int szA = (AMODE == 0) ? BM * SAn : BK * SAtA;
    constexpr int szB = (BMODE == 0) ? BN * SAn : BK * SAtB;
    constexpr int NAP = (NPROD == 3) ? 2 : 1;
    constexpr int NBP = (NPROD >= 2) ? 2 : 1;
    constexpr int OFF_BH_ = NAP * szA;
    constexpr int OFF_BL_ = OFF_BH_ + szB;
    constexpr int STG = NAP * szA + NBP * szB;

    extern __shared__ __nv_bfloat16 smh[];

    int tid = threadIdx.x;
    int wid = tid >> 5, lane = tid & 31;
    int wm = wid & 1, wn = wid >> 1;

    int zb = blockIdx.z / N_HEADS, zh = blockIdx.z % N_HEADS;
    const __nv_bfloat16* pAh = Ah + (long)zb * sAb + (long)zh * sAh;
    const __nv_bfloat16* pAl = (NPROD == 3) ? Al + (long)zb * sAb + (long)zh * sAh : nullptr;
    const __nv_bfloat16* pBh = Bh + (long)zb * sBb + (long)zh * sBh;
    const __nv_bfloat16* pBl = (NPROD >= 2) ? Bl + (long)zb * sBb + (long)zh * sBh : nullptr;
    long cOff = (long)zb * sCb + (long)zh * sCh;
    int bm = blockIdx.y * BM, bn = blockIdx.x * BN;

    float acc[MA][NA][4];
    #pragma unroll
    for (int i = 0; i < MA; i++)
        #pragma unroll
        for (int j = 0; j < NA; j++)
            #pragma unroll
            for (int e = 0; e < 4; e++) acc[i][j][e] = 0.f;

    auto loadA = [&](__nv_bfloat16* sd, const __nv_bfloat16* gp, int k0) {
        if (AMODE == 0) {
            #pragma unroll
            for (int j = 0; j < BM * 4; j += 128) {
                int id = tid + j, r = id >> 2, sg = id & 3;
                cp16(smem_u32(sd + r * SAn + sg * 8), gp + (long)(bm + r) * lda + k0 + sg * 8);
            }
        } else {
            constexpr int CPR = BM / 8;
            #pragma unroll
            for (int j = 0; j < BK * CPR; j += 128) {
                int id = tid + j, kk = id / CPR, sg = id % CPR;
                cp16(smem_u32(sd + kk * SAtA + sg * 8), gp + (long)(k0 + kk) * lda + bm + sg * 8);
            }
        }
    };
    auto loadB = [&](__nv_bfloat16* sd, const __nv_bfloat16* gp, int k0) {
        if (BMODE == 0) {
            #pragma unroll
            for (int j = 0; j < BN * 4; j += 128) {
                int id = tid + j, r = id >> 2, sg = id & 3;
                cp16(smem_u32(sd + r * SAn + sg * 8), gp + (long)(bn + r) * ldb + k0 + sg * 8);
            }
        } else {
            constexpr int CPR = BN / 8;
            #pragma unroll
            for (int j = 0; j < BK * CPR; j += 128) {
                int id = tid + j, kk = id / CPR, sg = id % CPR;
                cp16(smem_u32(sd + kk * SAtB + sg * 8), gp + (long)(k0 + kk) * ldb + bn + sg * 8);
            }
        }
    };
    auto prefetch = [&](__nv_bfloat16* st, int k0) {
        loadA(st, pAh, k0);
        if (NPROD == 3) loadA(st + szA, pAl, k0);
        loadB(st + OFF_BH_, pBh, k0);
        if (NPROD >= 2) loadB(st + OFF_BL_, pBl, k0);
        cp_commit();
    };

    auto compute = [&](const __nv_bfloat16* cur) {
        const __nv_bfloat16* As_ = cur;
        const __nv_bfloat16* Al_ = cur + szA;
        const __nv_bfloat16* Bs_ = cur + OFF_BH_;
        const __nv_bfloat16* Bl_ = cur + OFF_BL_;
        #pragma unroll
        for (int ks = 0; ks < 2; ks++) {
            int ko = ks * 16;
            // ---- load ALL fragments first ----
            uint32_t bhf[NA][2], blf[NA][2];
            #pragma unroll
            for (int pr = 0; pr < NA/2; pr++) {
                uint32_t r[4], rl[4];
                if (BMODE == 0) {
                    int q = lane >> 3, idx = lane & 7;
                    int nrow = wn * WTN + pr * 16 + (q >> 1) * 8 + idx;
                    int kcol = ko + (q & 1) * 8;
                    ldsm4(r, smem_u32(Bs_ + nrow * SAn + kcol));
                    if (NPROD >= 2) ldsm4(rl, smem_u32(Bl_ + nrow * SAn + kcol));
                } else {
                    int krow = ko + ((lane >> 3) & 1) * 8 + (lane & 7);
                    int ncol = wn * WTN + pr * 16 + (lane >> 4) * 8;
                    ldsm4t(r, smem_u32(Bs_ + krow * SAtB + ncol));
                    if (NPROD >= 2) ldsm4t(rl, smem_u32(Bl_ + krow * SAtB + ncol));
                }
                bhf[pr*2][0] = r[0];  bhf[pr*2][1] = r[1];
                bhf[pr*2+1][0] = r[2]; bhf[pr*2+1][1] = r[3];
                if (NPROD >= 2) {
                    blf[pr*2][0] = rl[0]; blf[pr*2][1] = rl[1];
                    blf[pr*2+1][0] = rl[2]; blf[pr*2+1][1] = rl[3];
                }
            }
            uint32_t ahf[MA][4], alf[MA][4];
            #pragma unroll
            for (int ma = 0; ma < MA; ma++) {
                if (AMODE == 0) {
                    int arow = wm * 64 + ma * 16 + (lane & 15);
                    int akcol = ko + (lane >> 4) * 8;
                    ldsm4(ahf[ma], smem_u32(As_ + arow * SAn + akcol));
                    if (NPROD == 3) ldsm4(alf[ma], smem_u32(Al_ + arow * SAn + akcol));
                } else {
                    int akrow = ko + (lane & 7) + (lane >> 4) * 8;
                    int amcol = wm * 64 + ma * 16 + ((lane >> 3) & 1) * 8;
                    ldsm4t(ahf[ma], smem_u32(As_ + akrow * SAtA + amcol));
                    if (NPROD == 3) ldsm4t(alf[ma], smem_u32(Al_ + akrow * SAtA + amcol));
                }
            }
            // ---- product-major MMA passes: all acc tiles independent within a pass ----
            #pragma unroll
            for (int ma = 0; ma < MA; ma++)
                #pragma unroll
                for (int na = 0; na < NA; na++)
                    MMA16816(acc[ma][na], ahf[ma], bhf[na]);
            if (NPROD >= 2) {
                #pragma unroll
                for (int ma = 0; ma < MA; ma++)
                    #pragma unroll
                    for (int na = 0; na < NA; na++)
                        MMA16816(acc[ma][na], ahf[ma], blf[na]);
            }
            if (NPROD == 3) {
                #pragma unroll
                for (int ma = 0; ma < MA; ma++)
                    #pragma unroll
                    for (int na = 0; na < NA; na++)
                        MMA16816(acc[ma][na], alf[ma], bhf[na]);
            }
        }
    };

    int nCh = K >> 5;
    prefetch(smh, 0);
    for (int c = 0; c < nCh; c++) {
        cp_wait<0>();
        __syncthreads();
        if (c + 1 < nCh) prefetch(smh + ((c + 1) & 1) * STG, (c + 1) << 5);
        compute(smh + (c & 1) * STG);
    }

    // ---- epilogue ----
    int g = lane >> 2, tig = lane & 3;
    float scale = (EPI == 5) ? betaP[zh] : 1.0f;
    #pragma unroll
    for (int ma = 0; ma < MA; ma++) {
        #pragma unroll
        for (int na = 0; na < NA; na++) {
            int r = bm + wm*64 + ma*16 + g;
            int cc = bn + wn*WTN + na*8 + tig*2;
            long o0 = cOff + (long)r*ldc + cc;
            long o1 = cOff + (long)(r+8)*ldc + cc;
            if (EPI == 0) {
                *(float2*)(C + o0) = float2{ acc[ma][na][0], acc[ma][na][1] };
                *(float2*)(C + o1) = float2{ acc[ma][na][2], acc[ma][na][3] };
            } else if (EPI == 5) {
                *(__nv_bfloat162*)(Ch + o0) = __nv_bfloat162{
                    __float2bfloat16_rn(acc[ma][na][0]*scale), __float2bfloat16_rn(acc[ma][na][1]*scale) };
                *(__nv_bfloat162*)(Ch + o1) = __nv_bfloat162{
                    __float2bfloat16_rn(acc[ma][na][2]*scale), __float2bfloat16_rn(acc[ma][na][3]*scale) };
            } else if (EPI == 6) {
                *(__nv_bfloat162*)(Ch + o0) = __nv_bfloat162{
                    __float2bfloat16_rn(acc[ma][na][0]), __float2bfloat16_rn(acc[ma][na][1]) };
                *(__nv_bfloat162*)(Ch + o1) = __nv_bfloat162{
                    __float2bfloat16_rn(acc[ma][na][2]), __float2bfloat16_rn(acc[ma][na][3]) };
            } else if (EPI == 4) {
                *(__nv_bfloat162*)(Ch + o0) = __nv_bfloat162{
                    __float2bfloat16_rn(fmaxf(acc[ma][na][0],0.f)), __float2bfloat16_rn(fmaxf(acc[ma][na][1],0.f)) };
                *(__nv_bfloat162*)(Ch + o1) = __nv_bfloat162{
                    __float2bfloat16_rn(fmaxf(acc[ma][na][2],0.f)), __float2bfloat16_rn(fmaxf(acc[ma][na][3],0.f)) };
            } else {
                float v0 = acc[ma][na][0], v1 = acc[ma][na][1];
                float v2 = acc[ma][na][2], v3 = acc[ma][na][3];
                if (EPI == 3) { v0 = fmaxf(v0,0.f); v1 = fmaxf(v1,0.f);
                                v2 = fmaxf(v2,0.f); v3 = fmaxf(v3,0.f); }
                __nv_bfloat16 h0,l0,h1,l1,h2,l2,h3,l3;
                split_val(v0,h0,l0); split_val(v1,h1,l1);
                split_val(v2,h2,l2); split_val(v3,h3,l3);
                *(__nv_bfloat162*)(Ch + o0) = __nv_bfloat162{h0, h1};
                *(__nv_bfloat162*)(Cl + o0) = __nv_bfloat162{l0, l1};
                *(__nv_bfloat162*)(Ch + o1) = __nv_bfloat162{h2, h3};
                *(__nv_bfloat162*)(Cl + o1) = __nv_bfloat162{l2, l3};
            }
        }
    }
}

// ---------------- driver ----------------
extern "C" void kernel_launch(void* const* d_in, const int* in_sizes, int n_in,
                              void* d_out, int out_size) {
    const float* x_in  = (const float*)d_in[0];
    const float* gamma = (const float*)d_in[1];
    const float* delta = (const float*)d_in[2];
    const float* Wq    = (const float*)d_in[3];
    const float* Wk    = (const float*)d_in[4];
    const float* beta  = (const float*)d_in[5];
    const float* xi    = (const float*)d_in[6];
    float* x = (float*)d_out;

    __nv_bfloat16* bh = nullptr; float* fp = nullptr;
    cudaGetSymbolAddress((void**)&bh, g_bh);
    cudaGetSymbolAddress((void**)&fp, g_fp);

    __nv_bfloat16 *GH = bh+O_GH, *GL = bh+O_GL, *QKH = bh+O_QKH;
    __nv_bfloat16 *PH = bh+O_PH, *ABH = bh+O_AB, *AQH = bh+O_AQH, *AQL = bh+O_AQL;
    __nv_bfloat16 *HH = bh+O_HH, *WH = bh+O_WH, *WL = bh+O_WL;
    __nv_bfloat16 *WTH = bh+O_WTH, *WTL = bh+O_WTL, *XH = bh+O_XH, *XL = bh+O_XL;
    __nv_bfloat16 *XTH = bh+O_XTH, *XTL = bh+O_XTL;
    float *Gattn = fp+F_GA, *Ghop = fp+F_GO;
    float *meanb = fp+F_MEAN, *rstd = fp+F_RSTD;

    constexpr int SM_N3   = (2*128*40 + 2*128*40) * 2 * 2;   // 81920 (Gattn)
    constexpr int SM_N2   = (1*128*40 + 2*128*40) * 2 * 2;   // 61440 (QK, H, Ghop)
    constexpr int SM_N1   = (1*128*40 + 1*128*40) * 2 * 2;   // 40960 (scores)
    constexpr int SM_AQ   = (1*128*40 + 1*32*72) * 2 * 2;    // 29696
    constexpr int SM_AK   = (1*32*136 + 1*32*72) * 2 * 2;    // 26624
    cudaFuncSetAttribute(mma_gemm<128,0,0,3,0>, cudaFuncAttributeMaxDynamicSharedMemorySize, SM_N3);
    cudaFuncSetAttribute(mma_gemm<128,0,0,2,6>, cudaFuncAttributeMaxDynamicSharedMemorySize, SM_N2);
    cudaFuncSetAttribute(mma_gemm<128,0,0,2,4>, cudaFuncAttributeMaxDynamicSharedMemorySize, SM_N2);
    cudaFuncSetAttribute(mma_gemm<128,0,0,2,0>, cudaFuncAttributeMaxDynamicSharedMemorySize, SM_N2);
    cudaFuncSetAttribute(mma_gemm<128,0,0,1,5>, cudaFuncAttributeMaxDynamicSharedMemorySize, SM_N1);
    cudaFuncSetAttribute(mma_gemm<64,0,2,1,2>,  cudaFuncAttributeMaxDynamicSharedMemorySize, SM_AQ);
    cudaFuncSetAttribute(mma_gemm<64,2,2,1,2>,  cudaFuncAttributeMaxDynamicSharedMemorySize, SM_AK);

    // ---- setup (constant across steps) ----
    cudaMemcpyAsync(x, x_in, sizeof(float) * NG, cudaMemcpyDeviceToDevice);
    split_mat<<<2304, 256>>>(Wq, WH, WL);
    split_mat<<<2304, 256>>>(Wk, WH + 768*768, WL + 768*768);
    split_mat<<<9216, 256>>>(xi, XH, XL);
    transpose_split<<<dim3(24,24), dim3(32,8)>>>(Wq, 768, 768, WTH, WTL, 1536, 0);
    transpose_split<<<dim3(24,24), dim3(32,8)>>>(Wk, 768, 768, WTH, WTL, 1536, 768);
    transpose_split<<<dim3(24,96), dim3(32,8)>>>(xi, 3072, 768, XTH, XTL, 3072, 0);

    // initial LN
    ln_forward<<<ROWS, 256>>>(x, gamma, delta, GH, GL, rstd, meanb);

    const long sQb = 1024L * 1536;
    const long sPz = (long)SS * SS;

    for (int step = 0; step < NSTEPS; step++) {
        // 1. QK = g @ Wqk^T  (2 products, hi-only out)
        mma_gemm<128,0,0,2,6><<<dim3(12,64,1), 128, SM_N2>>>(
            GH, GL, 768, 0, 0, WH, WL, 768, 0, 0,
            nullptr, QKH, nullptr, 1536, 0, 0, 768, nullptr);

        // 2. scores = beta_h * Q K^T -> bf16 (1 product)
        mma_gemm<128,0,0,1,5><<<dim3(8,8,ZB), 128, SM_N1>>>(
            QKH, nullptr, 1536, sQb, 64,
            QKH + 768, nullptr, 1536, sQb, 64,
            nullptr, ABH, nullptr, SS, (long)N_HEADS * sPz, sPz, 64, beta);

        // 3. fused softmax -> single P plane
        softmax_split<<<ZB * SS, 256>>>(ABH, PH);

        // 4. Aq = P @ K (1 product)
        mma_gemm<64,0,2,1,2><<<dim3(1,8,ZB), 128, SM_AQ>>>(
            PH, nullptr, SS, (long)N_HEADS * sPz, sPz,
            QKH + 768, nullptr, 1536, sQb, 64,
            nullptr, AQH, AQL, 1536, sQb, 64, SS, nullptr);

        // 5. Ak = P^T @ Q (1 product)
        mma_gemm<64,2,2,1,2><<<dim3(1,8,ZB), 128, SM_AK>>>(
            PH, nullptr, SS, (long)N_HEADS * sPz, sPz,
            QKH, nullptr, 1536, sQb, 64,
            nullptr, AQH + 768, AQL + 768, 1536, sQb, 64, SS, nullptr);

        // 6. Gattn = AqAk @ Wqk (3 products, fp32 out)
        mma_gemm<128,0,0,3,0><<<dim3(6,64,1), 128, SM_N3>>>(
            AQH, AQL, 1536, 0, 0, WTH, WTL, 1536, 0, 0,
            Gattn, nullptr, nullptr, 768, 0, 0, 1536, nullptr);

        // 7. H = relu(g @ xi^T) (2 products, hi-only out)
        mma_gemm<128,0,0,2,4><<<dim3(24,64,1), 128, SM_N2>>>(
            GH, GL, 768, 0, 0, XH, XL, 768, 0, 0,
            nullptr, HH, nullptr, 3072, 0, 0, 768, nullptr);

        // 8. Ghop = relu(H) @ xi (2 products, fp32 out)
        mma_gemm<128,0,0,2,0><<<dim3(6,64,1), 128, SM_N2>>>(
            HH, nullptr, 3072, 0, 0, XTH, XTL, 3072, 0, 0,
            Ghop, nullptr, nullptr, 768, 0, 0, 3072, nullptr);

        // 9. LN backward + SGD update (+ fused next-step LN forward)
        if (step < NSTEPS - 1)
            update_ln<true><<<ROWS, 256>>>(x, Gattn, Ghop, gamma, delta,
                                           meanb, rstd, GH, GL, rstd, meanb);
        else
            update_ln<false><<<ROWS, 256>>>(x, Gattn, Ghop, gamma, delta,
                                            meanb, rstd, nullptr, nullptr, nullptr, nullptr);
    }
}